// round 1
// baseline (speedup 1.0000x reference)
#include <cuda_runtime.h>
#include <math.h>

// Problem shape (SparseGatedMoE): x[B,D], w_gate[D,E], W1[E,D,H], b1[E,H], W2[E,H,D], b2[E,D]
constexpr int B = 8192;
constexpr int D = 512;
constexpr int E = 8;
constexpr int H = 2048;
constexpr int TOPK = 2;
constexpr int NA = B * TOPK;   // total expert assignments = 16384

// ---------------- device scratch (no allocations allowed) ----------------
__device__ float g_h[(size_t)NA * H];       // gelu(x@W1+b1) per assignment slot (~134 MB)
__device__ int   g_top_idx[B * TOPK];
__device__ float g_top_gate[B * TOPK];
__device__ int   g_counts[E];
__device__ int   g_offsets[E];
__device__ int   g_cursor[E];
__device__ int   g_assign_token[NA];
__device__ float g_assign_gate[NA];

// ---------------- phase 0: zero output + counters ----------------
__global__ void k_zero(float* __restrict__ y) {
    int i = blockIdx.x * blockDim.x + threadIdx.x;
    if (i < B * D) y[i] = 0.0f;
    if (i < E) g_counts[i] = 0;
}

// ---------------- phase 1: gating (logits, top-2, softmax, counts) ----------------
// grid: B/256 blocks, 256 threads. Each thread owns one token.
__global__ void k_gate(const float* __restrict__ x, const float* __restrict__ wgate) {
    __shared__ float wg[D * E];          // 16 KB
    __shared__ float xs[256 * 17];       // 256 tokens x 16 d-chunk, padded (17.4 KB)

    int t = threadIdx.x;
    int token = blockIdx.x * 256 + t;

    for (int i = t; i < D * E; i += 256) wg[i] = wgate[i];

    float logit[E];
#pragma unroll
    for (int e = 0; e < E; e++) logit[e] = 0.0f;

    for (int k0 = 0; k0 < D; k0 += 16) {
        __syncthreads();
        // coalesced stage: 256 rows x 16 cols
#pragma unroll
        for (int i = 0; i < 16; i++) {
            int idx = t + i * 256;             // 0..4095
            int r = idx >> 4;                  // token row in block
            int c = idx & 15;                  // d within chunk
            xs[r * 17 + c] = x[(size_t)(blockIdx.x * 256 + r) * D + k0 + c];
        }
        __syncthreads();
#pragma unroll
        for (int c = 0; c < 16; c++) {
            float xv = xs[t * 17 + c];
            const float* wrow = &wg[(k0 + c) * E];
#pragma unroll
            for (int e = 0; e < E; e++) logit[e] = fmaf(xv, wrow[e], logit[e]);
        }
    }

    // top-2 (first-occurrence on ties, matching lax.top_k)
    float v0 = logit[0]; int i0 = 0;
#pragma unroll
    for (int e = 1; e < E; e++) if (logit[e] > v0) { v0 = logit[e]; i0 = e; }
    float v1 = -3.4e38f; int i1 = 0;
#pragma unroll
    for (int e = 0; e < E; e++) if (e != i0 && logit[e] > v1) { v1 = logit[e]; i1 = e; }

    // softmax over [v0, v1]
    float e1 = __expf(v1 - v0);
    float inv = 1.0f / (1.0f + e1);
    float gate0 = inv, gate1 = e1 * inv;

    g_top_idx[token * 2 + 0] = i0;
    g_top_idx[token * 2 + 1] = i1;
    g_top_gate[token * 2 + 0] = gate0;
    g_top_gate[token * 2 + 1] = gate1;
    atomicAdd(&g_counts[i0], 1);
    atomicAdd(&g_counts[i1], 1);
}

// ---------------- phase 2: offsets (E=8 -> single thread) ----------------
__global__ void k_scan() {
    int off = 0;
    for (int e = 0; e < E; e++) {
        g_offsets[e] = off;
        g_cursor[e] = off;
        off += g_counts[e];
    }
}

// ---------------- phase 3: fill contiguous per-expert buckets ----------------
__global__ void k_fill() {
    int token = blockIdx.x * blockDim.x + threadIdx.x;
    if (token >= B) return;
#pragma unroll
    for (int k = 0; k < TOPK; k++) {
        int e = g_top_idx[token * 2 + k];
        int pos = atomicAdd(&g_cursor[e], 1);
        g_assign_token[pos] = token;
        g_assign_gate[pos] = g_top_gate[token * 2 + k];
    }
}

__device__ __forceinline__ float gelu_exact(float v) {
    return 0.5f * v * (1.0f + erff(v * 0.70710678118654752f));
}

// ---------------- phase 4: GEMM1  h = gelu(gather(x) @ W1[e] + b1[e]) ----------------
// tile 64x64, TK=16, 256 threads, 4x4 microtile
// grid: (H/64, 128, E)  -- early exit when row tile beyond bucket
__global__ void __launch_bounds__(256) k_gemm1(const float* __restrict__ x,
                                               const float* __restrict__ W1,
                                               const float* __restrict__ b1) {
    int e = blockIdx.z;
    int n_e = g_counts[e];
    int row0 = blockIdx.y * 64;
    if (row0 >= n_e) return;
    int off = g_offsets[e];
    int col0 = blockIdx.x * 64;

    __shared__ __align__(16) float As[16][64];   // [k][m]
    __shared__ __align__(16) float Bs[16][64];   // [k][n]

    int t = threadIdx.x;
    int tx = t & 15, ty = t >> 4;

    // A-load mapping: thread loads float4 of x row (ar) at k-offset ak
    int ar = t >> 2;            // 0..63
    int ak = (t & 3) * 4;       // 0,4,8,12
    int arow = row0 + ar;
    int tokA = (arow < n_e) ? g_assign_token[off + arow] : -1;

    // B-load mapping: thread loads float4 at (bk, bn)
    int bk = t >> 4;            // 0..15
    int bn = (t & 15) * 4;      // 0..60

    float acc[4][4];
#pragma unroll
    for (int i = 0; i < 4; i++)
#pragma unroll
        for (int j = 0; j < 4; j++) acc[i][j] = 0.0f;

    const float* Wbase = W1 + (size_t)e * D * H;

    for (int k0 = 0; k0 < D; k0 += 16) {
        float4 av = make_float4(0.f, 0.f, 0.f, 0.f);
        if (tokA >= 0) av = *(const float4*)&x[(size_t)tokA * D + k0 + ak];
        float4 bv = *(const float4*)&Wbase[(size_t)(k0 + bk) * H + col0 + bn];
        __syncthreads();
        As[ak + 0][ar] = av.x;
        As[ak + 1][ar] = av.y;
        As[ak + 2][ar] = av.z;
        As[ak + 3][ar] = av.w;
        *(float4*)&Bs[bk][bn] = bv;
        __syncthreads();
#pragma unroll
        for (int kk = 0; kk < 16; kk++) {
            float4 a = *(const float4*)&As[kk][ty * 4];
            float4 b = *(const float4*)&Bs[kk][tx * 4];
            float ar4[4] = {a.x, a.y, a.z, a.w};
            float br4[4] = {b.x, b.y, b.z, b.w};
#pragma unroll
            for (int i = 0; i < 4; i++)
#pragma unroll
                for (int j = 0; j < 4; j++)
                    acc[i][j] = fmaf(ar4[i], br4[j], acc[i][j]);
        }
    }

    float4 b1v = *(const float4*)&b1[(size_t)e * H + col0 + tx * 4];
#pragma unroll
    for (int i = 0; i < 4; i++) {
        int r = row0 + ty * 4 + i;
        if (r < n_e) {
            float4 o;
            o.x = gelu_exact(acc[i][0] + b1v.x);
            o.y = gelu_exact(acc[i][1] + b1v.y);
            o.z = gelu_exact(acc[i][2] + b1v.z);
            o.w = gelu_exact(acc[i][3] + b1v.w);
            *(float4*)&g_h[(size_t)(off + r) * H + col0 + tx * 4] = o;
        }
    }
}

// ---------------- phase 5: GEMM2  y += gate * (h @ W2[e] + b2[e]) ----------------
// grid: (D/64, 128, E)
__global__ void __launch_bounds__(256) k_gemm2(const float* __restrict__ W2,
                                               const float* __restrict__ b2,
                                               float* __restrict__ y) {
    int e = blockIdx.z;
    int n_e = g_counts[e];
    int row0 = blockIdx.y * 64;
    if (row0 >= n_e) return;
    int off = g_offsets[e];
    int col0 = blockIdx.x * 64;

    __shared__ __align__(16) float As[16][64];
    __shared__ __align__(16) float Bs[16][64];

    int t = threadIdx.x;
    int tx = t & 15, ty = t >> 4;

    int ar = t >> 2;
    int ak = (t & 3) * 4;
    int arow = row0 + ar;
    bool avalid = (arow < n_e);

    int bk = t >> 4;
    int bn = (t & 15) * 4;

    float acc[4][4];
#pragma unroll
    for (int i = 0; i < 4; i++)
#pragma unroll
        for (int j = 0; j < 4; j++) acc[i][j] = 0.0f;

    const float* Wbase = W2 + (size_t)e * H * D;
    const float* Abase = g_h + (size_t)(off + arow) * H;

    for (int k0 = 0; k0 < H; k0 += 16) {
        float4 av = make_float4(0.f, 0.f, 0.f, 0.f);
        if (avalid) av = *(const float4*)&Abase[k0 + ak];
        float4 bv = *(const float4*)&Wbase[(size_t)(k0 + bk) * D + col0 + bn];
        __syncthreads();
        As[ak + 0][ar] = av.x;
        As[ak + 1][ar] = av.y;
        As[ak + 2][ar] = av.z;
        As[ak + 3][ar] = av.w;
        *(float4*)&Bs[bk][bn] = bv;
        __syncthreads();
#pragma unroll
        for (int kk = 0; kk < 16; kk++) {
            float4 a = *(const float4*)&As[kk][ty * 4];
            float4 b = *(const float4*)&Bs[kk][tx * 4];
            float ar4[4] = {a.x, a.y, a.z, a.w};
            float br4[4] = {b.x, b.y, b.z, b.w};
#pragma unroll
            for (int i = 0; i < 4; i++)
#pragma unroll
                for (int j = 0; j < 4; j++)
                    acc[i][j] = fmaf(ar4[i], br4[j], acc[i][j]);
        }
    }

    float4 b2v = *(const float4*)&b2[(size_t)e * D + col0 + tx * 4];
#pragma unroll
    for (int i = 0; i < 4; i++) {
        int r = row0 + ty * 4 + i;
        if (r < n_e) {
            int tok = g_assign_token[off + r];
            float gate = g_assign_gate[off + r];
            float* yrow = &y[(size_t)tok * D + col0 + tx * 4];
            atomicAdd(&yrow[0], gate * (acc[i][0] + b2v.x));
            atomicAdd(&yrow[1], gate * (acc[i][1] + b2v.y));
            atomicAdd(&yrow[2], gate * (acc[i][2] + b2v.z));
            atomicAdd(&yrow[3], gate * (acc[i][3] + b2v.w));
        }
    }
}

extern "C" void kernel_launch(void* const* d_in, const int* in_sizes, int n_in,
                              void* d_out, int out_size) {
    const float* x     = (const float*)d_in[0];
    const float* wgate = (const float*)d_in[1];
    const float* W1    = (const float*)d_in[2];
    const float* b1    = (const float*)d_in[3];
    const float* W2    = (const float*)d_in[4];
    const float* b2    = (const float*)d_in[5];
    float* y = (float*)d_out;

    k_zero<<<(B * D + 255) / 256, 256>>>(y);
    k_gate<<<B / 256, 256>>>(x, wgate);
    k_scan<<<1, 1>>>();
    k_fill<<<(B + 255) / 256, 256>>>();

    // worst case per expert: all B tokens -> 128 row tiles of 64
    dim3 g1(H / 64, B / 64, E);
    k_gemm1<<<g1, 256>>>(x, W1, b1);
    dim3 g2(D / 64, B / 64, E);
    k_gemm2<<<g2, 256>>>(W2, b2, y);
}

// round 9
// speedup vs baseline: 2.5593x; 2.5593x over previous
#include <cuda_runtime.h>
#include <cstdint>
#include <math.h>

// Shapes: x[B,D], w_gate[D,E], W1[E,D,H], b1[E,H], W2[E,H,D], b2[E,D]
constexpr int B_ = 8192, D_ = 512, E_ = 8, H_ = 2048;
constexpr int NA = B_ * 2;                 // top-2 assignments = 16384

// GEMM tiling (mma.sync tf32 path)
constexpr int M_TILE = 128, N_TILE = 128, K_CHUNK = 32;
constexpr int MAX_TILES = NA / M_TILE + E_;      // 136
constexpr int A_SZ = M_TILE * K_CHUNK * 4;       // 16384 (K-major, 128B rows)
constexpr int B_SZ = N_TILE * K_CHUNK * 4;       // 16384 ([n][k] K-major)
constexpr int STG = A_SZ + B_SZ;                 // 32768 per stage
constexpr int SMEM_BYTES = 2 * STG + 512 + 1024; // 2 stages + tok + align

// ---------------- device scratch (NEVER passed as kernel args from host!) ----
__device__ float g_h[(size_t)NA * H_];     // gelu(xW1+b1) per assignment (~134MB)
__device__ float g_out[(size_t)NA * D_];   // per-assignment expert output (~34MB)
__device__ int   g_top_idx[NA];
__device__ float g_top_gate[NA];
__device__ int   g_slot[NA];
__device__ int   g_counts[E_], g_offsets[E_], g_cursor[E_];
__device__ int   g_assign_token[NA];
__device__ int   g_tile_expert[MAX_TILES], g_tile_row0[MAX_TILES];
__device__ int   g_n_tiles;

// ---------------- helpers ----------------
__device__ __forceinline__ uint32_t smem_u32(const void* p) {
    uint32_t a;
    asm("{ .reg .u64 t; cvta.to.shared.u64 t, %1; cvt.u32.u64 %0, t; }" : "=r"(a) : "l"(p));
    return a;
}
// K-major SW128 tile addressing: row has 128B (32 floats); atoms of 8 rows x 128B.
__device__ __forceinline__ uint32_t swz_addr(uint32_t tile_base, int row, int kbyte) {
    return tile_base + (((row & 7) << 7) | ((row >> 3) << 10)) + (kbyte ^ ((row & 7) << 4));
}
__device__ __forceinline__ float tf32r(float x) {
    float r; asm("cvt.rna.tf32.f32 %0, %1;" : "=f"(r) : "f"(x)); return r;
}
__device__ __forceinline__ void sts128(uint32_t a, float4 v) {
    asm volatile("st.shared.v4.b32 [%0], {%1,%2,%3,%4};"
                 :: "r"(a), "f"(v.x), "f"(v.y), "f"(v.z), "f"(v.w) : "memory");
}
__device__ __forceinline__ uint32_t lds32(uint32_t a) {
    uint32_t v;
    asm volatile("ld.shared.b32 %0, [%1];" : "=r"(v) : "r"(a));
    return v;
}
__device__ __forceinline__ void mma8(float* d, const uint32_t* a, const uint32_t* b) {
    asm volatile(
        "mma.sync.aligned.m16n8k8.row.col.f32.tf32.tf32.f32 "
        "{%0,%1,%2,%3}, {%4,%5,%6,%7}, {%8,%9}, {%0,%1,%2,%3};"
        : "+f"(d[0]), "+f"(d[1]), "+f"(d[2]), "+f"(d[3])
        : "r"(a[0]), "r"(a[1]), "r"(a[2]), "r"(a[3]), "r"(b[0]), "r"(b[1]));
}
__device__ __forceinline__ float gelu_exact(float v) {
    return 0.5f * v * (1.0f + erff(v * 0.70710678118654752f));
}

// ---------------- small kernels ----------------
__global__ void k_init() {
    if (threadIdx.x < E_) g_counts[threadIdx.x] = 0;
}

__global__ void k_gate(const float* __restrict__ x, const float* __restrict__ wgate) {
    __shared__ float wg[D_ * E_];
    __shared__ float xs[256 * 17];
    int t = threadIdx.x;
    int token = blockIdx.x * 256 + t;
    for (int i = t; i < D_ * E_; i += 256) wg[i] = wgate[i];
    float logit[E_];
#pragma unroll
    for (int e = 0; e < E_; e++) logit[e] = 0.0f;
    for (int k0 = 0; k0 < D_; k0 += 16) {
        __syncthreads();
#pragma unroll
        for (int i = 0; i < 16; i++) {
            int idx = t + i * 256;
            int r = idx >> 4, c = idx & 15;
            xs[r * 17 + c] = x[(size_t)(blockIdx.x * 256 + r) * D_ + k0 + c];
        }
        __syncthreads();
#pragma unroll
        for (int c = 0; c < 16; c++) {
            float xv = xs[t * 17 + c];
            const float* wrow = &wg[(k0 + c) * E_];
#pragma unroll
            for (int e = 0; e < E_; e++) logit[e] = fmaf(xv, wrow[e], logit[e]);
        }
    }
    float v0 = logit[0]; int i0 = 0;
#pragma unroll
    for (int e = 1; e < E_; e++) if (logit[e] > v0) { v0 = logit[e]; i0 = e; }
    float v1 = -3.4e38f; int i1 = 0;
#pragma unroll
    for (int e = 0; e < E_; e++) if (e != i0 && logit[e] > v1) { v1 = logit[e]; i1 = e; }
    float e1 = __expf(v1 - v0);
    float inv = 1.0f / (1.0f + e1);
    g_top_idx[token * 2 + 0] = i0;
    g_top_idx[token * 2 + 1] = i1;
    g_top_gate[token * 2 + 0] = inv;
    g_top_gate[token * 2 + 1] = e1 * inv;
    atomicAdd(&g_counts[i0], 1);
    atomicAdd(&g_counts[i1], 1);
}

__global__ void k_scan() {
    int off = 0, nt = 0;
    for (int e = 0; e < E_; e++) {
        g_offsets[e] = off;
        g_cursor[e] = off;
        int n = g_counts[e];
        for (int r = 0; r < n; r += M_TILE) {
            g_tile_expert[nt] = e;
            g_tile_row0[nt] = r;
            nt++;
        }
        off += n;
    }
    g_n_tiles = nt;
}

__global__ void k_fill() {
    int token = blockIdx.x * blockDim.x + threadIdx.x;
    if (token >= B_) return;
#pragma unroll
    for (int k = 0; k < 2; k++) {
        int e = g_top_idx[token * 2 + k];
        int pos = atomicAdd(&g_cursor[e], 1);
        g_assign_token[pos] = token;
        g_slot[token * 2 + k] = pos;
    }
}

__global__ void k_combine(float* __restrict__ y) {
    int i = blockIdx.x * blockDim.x + threadIdx.x;
    if (i >= B_ * (D_ / 4)) return;
    int tok = i / (D_ / 4), q = i % (D_ / 4);
    float g0 = g_top_gate[tok * 2 + 0], g1 = g_top_gate[tok * 2 + 1];
    int s0 = g_slot[tok * 2 + 0], s1 = g_slot[tok * 2 + 1];
    float4 a = *(const float4*)&g_out[(size_t)s0 * D_ + q * 4];
    float4 b = *(const float4*)&g_out[(size_t)s1 * D_ + q * 4];
    float4 v;
    v.x = g0 * a.x + g1 * b.x;
    v.y = g0 * a.y + g1 * b.y;
    v.z = g0 * a.z + g1 * b.z;
    v.w = g0 * a.w + g1 * b.w;
    *(float4*)&y[(size_t)tok * D_ + q * 4] = v;
}

// ---------------- tf32 mma.sync grouped GEMM ----------------
// GATHER=true : A = x (rows gathered by token), C = g_h, GELU applied.
// GATHER=false: A = g_h (bucket rows),          C = g_out.
// Scratch buffers are resolved INSIDE device code (device symbols) — never
// passed from host (host sees only the shadow address; GB300 ATS makes that
// a silent wrong-memory access instead of a crash).
template <bool GATHER, bool GELU>
__global__ void __launch_bounds__(256, 1)
k_moe_gemm(const float* __restrict__ X, const float* __restrict__ W,
           const float* __restrict__ bias, int lda, int ldb, int ldc, int Ktot) {
    const float* A = GATHER ? X : (const float*)g_h;
    float* C = GATHER ? (float*)g_h : (float*)g_out;

    extern __shared__ char smraw[];
    uint32_t sm0 = smem_u32(smraw);
    uint32_t base = (sm0 + 1023) & ~1023u;
    int* sm_tok = (int*)(smraw + (base - sm0) + 2 * STG);

    int tile = blockIdx.y;
    if (tile >= g_n_tiles) return;
    int e = g_tile_expert[tile];
    int row0 = g_tile_row0[tile];
    int off = g_offsets[e];
    int n_e = g_counts[e];
    int col0 = blockIdx.x * N_TILE;
    int t = threadIdx.x;
    int nch = Ktot / K_CHUNK;

    if (t < 128) {
        int r = row0 + t;
        if (r > n_e - 1) r = n_e - 1;
        sm_tok[t] = GATHER ? g_assign_token[off + r] : (off + r);
    }
    __syncthreads();

    // ---- staging thread mapping ----
    int arow = t >> 3;          // 0..31 (+32j)
    int kq = t & 7;             // 16B column
    const float* aptr[4];
#pragma unroll
    for (int j = 0; j < 4; j++)
        aptr[j] = A + (size_t)sm_tok[arow + 32 * j] * lda;

    int bn = t & 127;           // n within tile
    int bkh = (t >> 7) * 16;    // k half
    const float* bptr = W + (size_t)e * Ktot * ldb + col0 + bn;

    float4 av[4];
    float bv[16];

    // ---- compute thread mapping ----
    int wid = t >> 5, lane = t & 31;
    int m0 = (wid & 1) * 64;
    int n0 = (wid >> 1) * 32;
    int g = lane >> 2, tig = lane & 3;

    float acc[4][4][4];
#pragma unroll
    for (int mt = 0; mt < 4; mt++)
#pragma unroll
        for (int nt = 0; nt < 4; nt++)
#pragma unroll
            for (int i = 0; i < 4; i++) acc[mt][nt][i] = 0.0f;

    uint32_t af[4][4], bfr[4][2];

#define LDG_CHUNK(c)                                                          \
    {                                                                         \
        int k0_ = (c) * K_CHUNK;                                              \
        _Pragma("unroll") for (int j = 0; j < 4; j++)                         \
            av[j] = *(const float4*)(aptr[j] + k0_ + kq * 4);                 \
        _Pragma("unroll") for (int i = 0; i < 16; i++)                        \
            bv[i] = bptr[(size_t)(k0_ + bkh + i) * ldb];                      \
    }
#define STS_CHUNK(s)                                                          \
    {                                                                         \
        uint32_t ab_ = base + (s) * STG, bb_ = ab_ + A_SZ;                    \
        _Pragma("unroll") for (int j = 0; j < 4; j++) {                       \
            float4 v = av[j];                                                 \
            v.x = tf32r(v.x); v.y = tf32r(v.y);                               \
            v.z = tf32r(v.z); v.w = tf32r(v.w);                               \
            sts128(swz_addr(ab_, arow + 32 * j, kq << 4), v);                 \
        }                                                                     \
        _Pragma("unroll") for (int g4 = 0; g4 < 4; g4++) {                    \
            float4 v;                                                         \
            v.x = tf32r(bv[4 * g4 + 0]); v.y = tf32r(bv[4 * g4 + 1]);         \
            v.z = tf32r(bv[4 * g4 + 2]); v.w = tf32r(bv[4 * g4 + 3]);         \
            sts128(swz_addr(bb_, bn, (bkh + 4 * g4) << 2), v);                \
        }                                                                     \
    }

    LDG_CHUNK(0);
    STS_CHUNK(0);
    LDG_CHUNK(1);

    for (int c = 0; c < nch; c++) {
        __syncthreads();
        if (c + 1 < nch) STS_CHUNK((c + 1) & 1);
        if (c + 2 < nch) LDG_CHUNK(c + 2);
        uint32_t ab_ = base + (c & 1) * STG;
        uint32_t bb_ = ab_ + A_SZ;
#pragma unroll
        for (int ks = 0; ks < 4; ks++) {
            int kb0 = (ks * 8 + tig) * 4;   // byte offset of this lane's k element
            // A fragments (PTX m16n8k8 tf32 map):
            // a0=(g,t) a1=(g+8,t) a2=(g,t+4) a3=(g+8,t+4); t+4 -> +16B
#pragma unroll
            for (int mt = 0; mt < 4; mt++) {
                int row = m0 + mt * 16 + g;
                af[mt][0] = lds32(swz_addr(ab_, row,     kb0));
                af[mt][1] = lds32(swz_addr(ab_, row + 8, kb0));
                af[mt][2] = lds32(swz_addr(ab_, row,     kb0 + 16));
                af[mt][3] = lds32(swz_addr(ab_, row + 8, kb0 + 16));
            }
            // B fragments: b0=(k=t, n=g), b1=(k=t+4, n=g); smem B stored [n][k]
#pragma unroll
            for (int nt = 0; nt < 4; nt++) {
                int n = n0 + nt * 8 + g;
                bfr[nt][0] = lds32(swz_addr(bb_, n, kb0));
                bfr[nt][1] = lds32(swz_addr(bb_, n, kb0 + 16));
            }
#pragma unroll
            for (int mt = 0; mt < 4; mt++)
#pragma unroll
                for (int nt = 0; nt < 4; nt++)
                    mma8(acc[mt][nt], af[mt], bfr[nt]);
        }
    }

    // ---- epilogue ----
    // c0=(g,2t) c1=(g,2t+1) c2=(g+8,2t) c3=(g+8,2t+1)
    const float* brow = bias + (size_t)e * ldb + col0;
    float2 bz[4];
#pragma unroll
    for (int nt = 0; nt < 4; nt++) {
        int col = n0 + nt * 8 + 2 * tig;
        bz[nt].x = brow[col];
        bz[nt].y = brow[col + 1];
    }
#pragma unroll
    for (int mt = 0; mt < 4; mt++) {
#pragma unroll
        for (int h = 0; h < 2; h++) {
            int r = row0 + m0 + mt * 16 + g + h * 8;
            if (r < n_e) {
                float* crow = C + (size_t)(off + r) * ldc + col0;
#pragma unroll
                for (int nt = 0; nt < 4; nt++) {
                    float v0 = acc[mt][nt][h * 2 + 0] + bz[nt].x;
                    float v1 = acc[mt][nt][h * 2 + 1] + bz[nt].y;
                    if (GELU) { v0 = gelu_exact(v0); v1 = gelu_exact(v1); }
                    float2 o; o.x = v0; o.y = v1;
                    *(float2*)(crow + n0 + nt * 8 + 2 * tig) = o;
                }
            }
        }
    }
#undef LDG_CHUNK
#undef STS_CHUNK
}

// ---------------- launch ----------------
extern "C" void kernel_launch(void* const* d_in, const int* in_sizes, int n_in,
                              void* d_out, int out_size) {
    const float* x     = (const float*)d_in[0];
    const float* wgate = (const float*)d_in[1];
    const float* W1    = (const float*)d_in[2];
    const float* b1    = (const float*)d_in[3];
    const float* W2    = (const float*)d_in[4];
    const float* b2    = (const float*)d_in[5];
    float* y = (float*)d_out;

    cudaFuncSetAttribute(k_moe_gemm<true, true>,
                         cudaFuncAttributeMaxDynamicSharedMemorySize, SMEM_BYTES);
    cudaFuncSetAttribute(k_moe_gemm<false, false>,
                         cudaFuncAttributeMaxDynamicSharedMemorySize, SMEM_BYTES);

    k_init<<<1, 32>>>();
    k_gate<<<B_ / 256, 256>>>(x, wgate);
    k_scan<<<1, 1>>>();
    k_fill<<<(B_ + 255) / 256, 256>>>();

    // GEMM1: A=x (gather), W=W1 [D,H], C=g_h  — lda=D, ldb=H, ldc=H, Ktot=D
    dim3 g1(H_ / N_TILE, MAX_TILES);   // (16, 136)
    k_moe_gemm<true, true><<<g1, 256, SMEM_BYTES>>>(x, W1, b1, D_, H_, H_, D_);
    // GEMM2: A=g_h, W=W2 [H,D], C=g_out — lda=H, ldb=D, ldc=D, Ktot=H
    dim3 g2(D_ / N_TILE, MAX_TILES);   // (4, 136)
    k_moe_gemm<false, false><<<g2, 256, SMEM_BYTES>>>(x, W2, b2, H_, D_, D_, H_);

    k_combine<<<(B_ * (D_ / 4) + 255) / 256, 256>>>(y);
}

// round 10
// speedup vs baseline: 2.7691x; 1.0820x over previous
#include <cuda_runtime.h>
#include <cstdint>
#include <math.h>

// Shapes: x[B,D], w_gate[D,E], W1[E,D,H], b1[E,H], W2[E,H,D], b2[E,D]
constexpr int B_ = 8192, D_ = 512, E_ = 8, H_ = 2048;
constexpr int NA = B_ * 2;                 // top-2 assignments = 16384

// GEMM tiling (mma.sync tf32 path)
constexpr int M_TILE = 128, N_TILE = 128, K_CHUNK = 32;
constexpr int MAX_TILES = NA / M_TILE + E_;      // 136
constexpr int A_SZ = M_TILE * K_CHUNK * 4;       // 16384 (K-major, 128B rows)
constexpr int B_SZ = N_TILE * K_CHUNK * 4;       // 16384 ([n][k] K-major)
constexpr int STG = A_SZ + B_SZ;                 // 32768 per stage
constexpr int SMEM_BYTES = 2 * STG + 512 + 1024; // 2 stages + tok + align

// ---------------- device scratch (NEVER passed as kernel args from host!) ----
__device__ float g_h[(size_t)NA * H_];     // gelu(xW1+b1) per assignment (~134MB)
__device__ float g_out[(size_t)NA * D_];   // per-assignment expert output (~34MB)
__device__ int   g_top_idx[NA];
__device__ float g_top_gate[NA];
__device__ int   g_slot[NA];
__device__ int   g_counts[E_], g_offsets[E_], g_cursor[E_];
__device__ int   g_assign_token[NA];
__device__ int   g_tile_expert[MAX_TILES], g_tile_row0[MAX_TILES];
__device__ int   g_n_tiles;

// ---------------- helpers ----------------
__device__ __forceinline__ uint32_t smem_u32(const void* p) {
    uint32_t a;
    asm("{ .reg .u64 t; cvta.to.shared.u64 t, %1; cvt.u32.u64 %0, t; }" : "=r"(a) : "l"(p));
    return a;
}
// K-major SW128 tile addressing: row has 128B (32 floats); atoms of 8 rows x 128B.
__device__ __forceinline__ uint32_t swz_addr(uint32_t tile_base, int row, int kbyte) {
    return tile_base + (((row & 7) << 7) | ((row >> 3) << 10)) + (kbyte ^ ((row & 7) << 4));
}
__device__ __forceinline__ float tf32r(float x) {
    float r; asm("cvt.rna.tf32.f32 %0, %1;" : "=f"(r) : "f"(x)); return r;
}
__device__ __forceinline__ void sts128(uint32_t a, float4 v) {
    asm volatile("st.shared.v4.b32 [%0], {%1,%2,%3,%4};"
                 :: "r"(a), "f"(v.x), "f"(v.y), "f"(v.z), "f"(v.w) : "memory");
}
__device__ __forceinline__ void ldsm4(uint32_t* r, uint32_t addr) {
    asm volatile("ldmatrix.sync.aligned.m8n8.x4.shared.b16 {%0,%1,%2,%3}, [%4];"
                 : "=r"(r[0]), "=r"(r[1]), "=r"(r[2]), "=r"(r[3]) : "r"(addr));
}
__device__ __forceinline__ void mma8(float* d, const uint32_t* a, const uint32_t* b) {
    asm volatile(
        "mma.sync.aligned.m16n8k8.row.col.f32.tf32.tf32.f32 "
        "{%0,%1,%2,%3}, {%4,%5,%6,%7}, {%8,%9}, {%0,%1,%2,%3};"
        : "+f"(d[0]), "+f"(d[1]), "+f"(d[2]), "+f"(d[3])
        : "r"(a[0]), "r"(a[1]), "r"(a[2]), "r"(a[3]), "r"(b[0]), "r"(b[1]));
}
__device__ __forceinline__ float gelu_exact(float v) {
    return 0.5f * v * (1.0f + erff(v * 0.70710678118654752f));
}

// ---------------- small kernels ----------------
__global__ void k_init() {
    if (threadIdx.x < E_) g_counts[threadIdx.x] = 0;
}

__global__ void k_gate(const float* __restrict__ x, const float* __restrict__ wgate) {
    __shared__ float wg[D_ * E_];
    __shared__ float xs[256 * 17];
    int t = threadIdx.x;
    int token = blockIdx.x * 256 + t;
    for (int i = t; i < D_ * E_; i += 256) wg[i] = wgate[i];
    float logit[E_];
#pragma unroll
    for (int e = 0; e < E_; e++) logit[e] = 0.0f;
    for (int k0 = 0; k0 < D_; k0 += 16) {
        __syncthreads();
#pragma unroll
        for (int i = 0; i < 16; i++) {
            int idx = t + i * 256;
            int r = idx >> 4, c = idx & 15;
            xs[r * 17 + c] = x[(size_t)(blockIdx.x * 256 + r) * D_ + k0 + c];
        }
        __syncthreads();
#pragma unroll
        for (int c = 0; c < 16; c++) {
            float xv = xs[t * 17 + c];
            const float* wrow = &wg[(k0 + c) * E_];
#pragma unroll
            for (int e = 0; e < E_; e++) logit[e] = fmaf(xv, wrow[e], logit[e]);
        }
    }
    float v0 = logit[0]; int i0 = 0;
#pragma unroll
    for (int e = 1; e < E_; e++) if (logit[e] > v0) { v0 = logit[e]; i0 = e; }
    float v1 = -3.4e38f; int i1 = 0;
#pragma unroll
    for (int e = 0; e < E_; e++) if (e != i0 && logit[e] > v1) { v1 = logit[e]; i1 = e; }
    float e1 = __expf(v1 - v0);
    float inv = 1.0f / (1.0f + e1);
    g_top_idx[token * 2 + 0] = i0;
    g_top_idx[token * 2 + 1] = i1;
    g_top_gate[token * 2 + 0] = inv;
    g_top_gate[token * 2 + 1] = e1 * inv;
    atomicAdd(&g_counts[i0], 1);
    atomicAdd(&g_counts[i1], 1);
}

__global__ void k_scan() {
    int off = 0, nt = 0;
    for (int e = 0; e < E_; e++) {
        g_offsets[e] = off;
        g_cursor[e] = off;
        int n = g_counts[e];
        for (int r = 0; r < n; r += M_TILE) {
            g_tile_expert[nt] = e;
            g_tile_row0[nt] = r;
            nt++;
        }
        off += n;
    }
    g_n_tiles = nt;
}

__global__ void k_fill() {
    int token = blockIdx.x * blockDim.x + threadIdx.x;
    if (token >= B_) return;
#pragma unroll
    for (int k = 0; k < 2; k++) {
        int e = g_top_idx[token * 2 + k];
        int pos = atomicAdd(&g_cursor[e], 1);
        g_assign_token[pos] = token;
        g_slot[token * 2 + k] = pos;
    }
}

__global__ void k_combine(float* __restrict__ y) {
    int i = blockIdx.x * blockDim.x + threadIdx.x;
    if (i >= B_ * (D_ / 4)) return;
    int tok = i / (D_ / 4), q = i % (D_ / 4);
    float g0 = g_top_gate[tok * 2 + 0], g1 = g_top_gate[tok * 2 + 1];
    int s0 = g_slot[tok * 2 + 0], s1 = g_slot[tok * 2 + 1];
    float4 a = *(const float4*)&g_out[(size_t)s0 * D_ + q * 4];
    float4 b = *(const float4*)&g_out[(size_t)s1 * D_ + q * 4];
    float4 v;
    v.x = g0 * a.x + g1 * b.x;
    v.y = g0 * a.y + g1 * b.y;
    v.z = g0 * a.z + g1 * b.z;
    v.w = g0 * a.w + g1 * b.w;
    *(float4*)&y[(size_t)tok * D_ + q * 4] = v;
}

// ---------------- tf32 mma.sync grouped GEMM ----------------
// GATHER=true : A = x (rows gathered by token), C = g_h, GELU applied.
// GATHER=false: A = g_h (bucket rows),          C = g_out.
// Scratch resolved via device symbols in device code only.
// Fragments loaded with ldmatrix.x4 (4x fewer load issues than scalar LDS).
template <bool GATHER, bool GELU>
__global__ void __launch_bounds__(256, 1)
k_moe_gemm(const float* __restrict__ X, const float* __restrict__ W,
           const float* __restrict__ bias, int lda, int ldb, int ldc, int Ktot) {
    const float* A = GATHER ? X : (const float*)g_h;
    float* C = GATHER ? (float*)g_h : (float*)g_out;

    extern __shared__ char smraw[];
    uint32_t sm0 = smem_u32(smraw);
    uint32_t base = (sm0 + 1023) & ~1023u;
    int* sm_tok = (int*)(smraw + (base - sm0) + 2 * STG);

    int tile = blockIdx.y;
    if (tile >= g_n_tiles) return;
    int e = g_tile_expert[tile];
    int row0 = g_tile_row0[tile];
    int off = g_offsets[e];
    int n_e = g_counts[e];
    int col0 = blockIdx.x * N_TILE;
    int t = threadIdx.x;
    int nch = Ktot / K_CHUNK;

    if (t < 128) {
        int r = row0 + t;
        if (r > n_e - 1) r = n_e - 1;
        sm_tok[t] = GATHER ? g_assign_token[off + r] : (off + r);
    }
    __syncthreads();

    // ---- staging thread mapping ----
    int arow = t >> 3;          // 0..31 (+32j)
    int kq = t & 7;             // 16B column
    const float* aptr[4];
#pragma unroll
    for (int j = 0; j < 4; j++)
        aptr[j] = A + (size_t)sm_tok[arow + 32 * j] * lda;

    int bn = t & 127;           // n within tile
    int bkh = (t >> 7) * 16;    // k half
    const float* bptr = W + (size_t)e * Ktot * ldb + col0 + bn;

    float4 av[4];
    float bv[16];

    // ---- compute thread mapping ----
    int wid = t >> 5, lane = t & 31;
    int m0 = (wid & 1) * 64;
    int n0 = (wid >> 1) * 32;
    // ldmatrix address lanes:
    // A x4: m0={rows 0-7,kb+0} m1={rows 8-15,kb+0} m2={rows 0-7,kb+16} m3={rows 8-15,kb+16}
    int a_row_l = (lane & 7) + ((lane >> 3) & 1) * 8;
    int a_kb_l = (lane >> 4) * 16;
    // B x4: m0={n 0-7,kb+0} m1={n 0-7,kb+16} m2={n 8-15,kb+0} m3={n 8-15,kb+16}
    int b_row_l = (lane & 7) + (lane >> 4) * 8;
    int b_kb_l = ((lane >> 3) & 1) * 16;
    int g = lane >> 2, tig = lane & 3;

    float acc[4][4][4];
#pragma unroll
    for (int mt = 0; mt < 4; mt++)
#pragma unroll
        for (int nt = 0; nt < 4; nt++)
#pragma unroll
            for (int i = 0; i < 4; i++) acc[mt][nt][i] = 0.0f;

    uint32_t af[4][4], bfr[4][2];

#define LDG_CHUNK(c)                                                          \
    {                                                                         \
        int k0_ = (c) * K_CHUNK;                                              \
        _Pragma("unroll") for (int j = 0; j < 4; j++)                         \
            av[j] = *(const float4*)(aptr[j] + k0_ + kq * 4);                 \
        _Pragma("unroll") for (int i = 0; i < 16; i++)                        \
            bv[i] = bptr[(size_t)(k0_ + bkh + i) * ldb];                      \
    }
#define STS_CHUNK(s)                                                          \
    {                                                                         \
        uint32_t ab_ = base + (s) * STG, bb_ = ab_ + A_SZ;                    \
        _Pragma("unroll") for (int j = 0; j < 4; j++) {                       \
            float4 v = av[j];                                                 \
            v.x = tf32r(v.x); v.y = tf32r(v.y);                               \
            v.z = tf32r(v.z); v.w = tf32r(v.w);                               \
            sts128(swz_addr(ab_, arow + 32 * j, kq << 4), v);                 \
        }                                                                     \
        _Pragma("unroll") for (int g4 = 0; g4 < 4; g4++) {                    \
            float4 v;                                                         \
            v.x = tf32r(bv[4 * g4 + 0]); v.y = tf32r(bv[4 * g4 + 1]);         \
            v.z = tf32r(bv[4 * g4 + 2]); v.w = tf32r(bv[4 * g4 + 3]);         \
            sts128(swz_addr(bb_, bn, (bkh + 4 * g4) << 2), v);                \
        }                                                                     \
    }

    LDG_CHUNK(0);
    STS_CHUNK(0);
    LDG_CHUNK(1);

    for (int c = 0; c < nch; c++) {
        __syncthreads();
        if (c + 1 < nch) STS_CHUNK((c + 1) & 1);
        if (c + 2 < nch) LDG_CHUNK(c + 2);
        uint32_t ab_ = base + (c & 1) * STG;
        uint32_t bb_ = ab_ + A_SZ;
#pragma unroll
        for (int ks = 0; ks < 4; ks++) {
            int kb = ks * 32;
            // A fragments: one ldmatrix.x4 per 16-row m-tile covers
            // a0=(g,tig) a1=(g+8,tig) a2=(g,tig+4) a3=(g+8,tig+4)
#pragma unroll
            for (int mt = 0; mt < 4; mt++)
                ldsm4(af[mt], swz_addr(ab_, m0 + mt * 16 + a_row_l, kb + a_kb_l));
            // B fragments: one ldmatrix.x4 covers two n-tiles (b0,b1 each)
#pragma unroll
            for (int nt2 = 0; nt2 < 2; nt2++) {
                uint32_t r4[4];
                ldsm4(r4, swz_addr(bb_, n0 + nt2 * 16 + b_row_l, kb + b_kb_l));
                bfr[2 * nt2 + 0][0] = r4[0]; bfr[2 * nt2 + 0][1] = r4[1];
                bfr[2 * nt2 + 1][0] = r4[2]; bfr[2 * nt2 + 1][1] = r4[3];
            }
#pragma unroll
            for (int mt = 0; mt < 4; mt++)
#pragma unroll
                for (int nt = 0; nt < 4; nt++)
                    mma8(acc[mt][nt], af[mt], bfr[nt]);
        }
    }

    // ---- epilogue ----
    // c0=(g,2t) c1=(g,2t+1) c2=(g+8,2t) c3=(g+8,2t+1)
    const float* brow = bias + (size_t)e * ldb + col0;
    float2 bz[4];
#pragma unroll
    for (int nt = 0; nt < 4; nt++) {
        int col = n0 + nt * 8 + 2 * tig;
        bz[nt].x = brow[col];
        bz[nt].y = brow[col + 1];
    }
#pragma unroll
    for (int mt = 0; mt < 4; mt++) {
#pragma unroll
        for (int h = 0; h < 2; h++) {
            int r = row0 + m0 + mt * 16 + g + h * 8;
            if (r < n_e) {
                float* crow = C + (size_t)(off + r) * ldc + col0;
#pragma unroll
                for (int nt = 0; nt < 4; nt++) {
                    float v0 = acc[mt][nt][h * 2 + 0] + bz[nt].x;
                    float v1 = acc[mt][nt][h * 2 + 1] + bz[nt].y;
                    if (GELU) { v0 = gelu_exact(v0); v1 = gelu_exact(v1); }
                    float2 o; o.x = v0; o.y = v1;
                    *(float2*)(crow + n0 + nt * 8 + 2 * tig) = o;
                }
            }
        }
    }
#undef LDG_CHUNK
#undef STS_CHUNK
}

// ---------------- launch ----------------
extern "C" void kernel_launch(void* const* d_in, const int* in_sizes, int n_in,
                              void* d_out, int out_size) {
    const float* x     = (const float*)d_in[0];
    const float* wgate = (const float*)d_in[1];
    const float* W1    = (const float*)d_in[2];
    const float* b1    = (const float*)d_in[3];
    const float* W2    = (const float*)d_in[4];
    const float* b2    = (const float*)d_in[5];
    float* y = (float*)d_out;

    cudaFuncSetAttribute(k_moe_gemm<true, true>,
                         cudaFuncAttributeMaxDynamicSharedMemorySize, SMEM_BYTES);
    cudaFuncSetAttribute(k_moe_gemm<false, false>,
                         cudaFuncAttributeMaxDynamicSharedMemorySize, SMEM_BYTES);

    k_init<<<1, 32>>>();
    k_gate<<<B_ / 256, 256>>>(x, wgate);
    k_scan<<<1, 1>>>();
    k_fill<<<(B_ + 255) / 256, 256>>>();

    // GEMM1: A=x (gather), W=W1 [D,H], C=g_h  — lda=D, ldb=H, ldc=H, Ktot=D
    dim3 g1(H_ / N_TILE, MAX_TILES);   // (16, 136)
    k_moe_gemm<true, true><<<g1, 256, SMEM_BYTES>>>(x, W1, b1, D_, H_, H_, D_);
    // GEMM2: A=g_h, W=W2 [H,D], C=g_out — lda=H, ldb=D, ldc=D, Ktot=H
    dim3 g2(D_ / N_TILE, MAX_TILES);   // (4, 136)
    k_moe_gemm<false, false><<<g2, 256, SMEM_BYTES>>>(x, W2, b2, H_, D_, D_, H_);

    k_combine<<<(B_ * (D_ / 4) + 255) / 256, 256>>>(y);
}

// round 11
// speedup vs baseline: 3.0572x; 1.1040x over previous
#include <cuda_runtime.h>
#include <cstdint>
#include <math.h>

// Shapes: x[B,D], w_gate[D,E], W1[E,D,H], b1[E,H], W2[E,H,D], b2[E,D]
constexpr int B_ = 8192, D_ = 512, E_ = 8, H_ = 2048;
constexpr int NA = B_ * 2;                 // top-2 assignments = 16384

// GEMM tiling (mma.sync tf32 path)
constexpr int M_TILE = 128, N_TILE = 128, K_CHUNK = 32;
constexpr int MAX_TILES = NA / M_TILE + E_;      // 136
constexpr int A_SZ = M_TILE * K_CHUNK * 4;       // 16384 (K-major, 128B rows)
constexpr int B_SZ = N_TILE * K_CHUNK * 4;       // 16384 ([n][k] K-major)
constexpr int STG = A_SZ + B_SZ;                 // 32768 per stage
constexpr int SMEM_BYTES = 2 * STG + 512 + 1024; // 2 stages + tok + align

// ---------------- device scratch (NEVER passed as kernel args from host!) ----
__device__ float g_h[(size_t)NA * H_];     // gelu(xW1+b1) per assignment (~134MB)
__device__ float g_out[(size_t)NA * D_];   // per-assignment expert output (~34MB)
__device__ int   g_top_idx[NA];
__device__ float g_top_gate[NA];
__device__ int   g_slot[NA];
__device__ int   g_counts[E_], g_offsets[E_], g_cursor[E_];
__device__ int   g_assign_token[NA];
__device__ int   g_tile_expert[MAX_TILES], g_tile_row0[MAX_TILES];
__device__ int   g_n_tiles;

// ---------------- helpers ----------------
__device__ __forceinline__ uint32_t smem_u32(const void* p) {
    uint32_t a;
    asm("{ .reg .u64 t; cvta.to.shared.u64 t, %1; cvt.u32.u64 %0, t; }" : "=r"(a) : "l"(p));
    return a;
}
// K-major SW128 tile addressing: row has 128B (32 floats); atoms of 8 rows x 128B.
__device__ __forceinline__ uint32_t swz_addr(uint32_t tile_base, int row, int kbyte) {
    return tile_base + (((row & 7) << 7) | ((row >> 3) << 10)) + (kbyte ^ ((row & 7) << 4));
}
__device__ __forceinline__ float tf32r(float x) {
    float r; asm("cvt.rna.tf32.f32 %0, %1;" : "=f"(r) : "f"(x)); return r;
}
__device__ __forceinline__ void sts128(uint32_t a, float4 v) {
    asm volatile("st.shared.v4.b32 [%0], {%1,%2,%3,%4};"
                 :: "r"(a), "f"(v.x), "f"(v.y), "f"(v.z), "f"(v.w) : "memory");
}
__device__ __forceinline__ void ldsm4(uint32_t* r, uint32_t addr) {
    asm volatile("ldmatrix.sync.aligned.m8n8.x4.shared.b16 {%0,%1,%2,%3}, [%4];"
                 : "=r"(r[0]), "=r"(r[1]), "=r"(r[2]), "=r"(r[3]) : "r"(addr));
}
__device__ __forceinline__ void mma8(float* d, const uint32_t* a, const uint32_t* b) {
    asm volatile(
        "mma.sync.aligned.m16n8k8.row.col.f32.tf32.tf32.f32 "
        "{%0,%1,%2,%3}, {%4,%5,%6,%7}, {%8,%9}, {%0,%1,%2,%3};"
        : "+f"(d[0]), "+f"(d[1]), "+f"(d[2]), "+f"(d[3])
        : "r"(a[0]), "r"(a[1]), "r"(a[2]), "r"(a[3]), "r"(b[0]), "r"(b[1]));
}
__device__ __forceinline__ float gelu_exact(float v) {
    return 0.5f * v * (1.0f + erff(v * 0.70710678118654752f));
}

// ---------------- small kernels ----------------
__global__ void k_init() {
    if (threadIdx.x < E_) g_counts[threadIdx.x] = 0;
}

__global__ void k_gate(const float* __restrict__ x, const float* __restrict__ wgate) {
    __shared__ float wg[D_ * E_];
    __shared__ float xs[256 * 17];
    int t = threadIdx.x;
    int token = blockIdx.x * 256 + t;
    for (int i = t; i < D_ * E_; i += 256) wg[i] = wgate[i];
    float logit[E_];
#pragma unroll
    for (int e = 0; e < E_; e++) logit[e] = 0.0f;
    for (int k0 = 0; k0 < D_; k0 += 16) {
        __syncthreads();
#pragma unroll
        for (int i = 0; i < 16; i++) {
            int idx = t + i * 256;
            int r = idx >> 4, c = idx & 15;
            xs[r * 17 + c] = x[(size_t)(blockIdx.x * 256 + r) * D_ + k0 + c];
        }
        __syncthreads();
#pragma unroll
        for (int c = 0; c < 16; c++) {
            float xv = xs[t * 17 + c];
            const float* wrow = &wg[(k0 + c) * E_];
#pragma unroll
            for (int e = 0; e < E_; e++) logit[e] = fmaf(xv, wrow[e], logit[e]);
        }
    }
    float v0 = logit[0]; int i0 = 0;
#pragma unroll
    for (int e = 1; e < E_; e++) if (logit[e] > v0) { v0 = logit[e]; i0 = e; }
    float v1 = -3.4e38f; int i1 = 0;
#pragma unroll
    for (int e = 0; e < E_; e++) if (e != i0 && logit[e] > v1) { v1 = logit[e]; i1 = e; }
    float e1 = __expf(v1 - v0);
    float inv = 1.0f / (1.0f + e1);
    g_top_idx[token * 2 + 0] = i0;
    g_top_idx[token * 2 + 1] = i1;
    g_top_gate[token * 2 + 0] = inv;
    g_top_gate[token * 2 + 1] = e1 * inv;
    atomicAdd(&g_counts[i0], 1);
    atomicAdd(&g_counts[i1], 1);
}

__global__ void k_scan() {
    int off = 0, nt = 0;
    for (int e = 0; e < E_; e++) {
        g_offsets[e] = off;
        g_cursor[e] = off;
        int n = g_counts[e];
        for (int r = 0; r < n; r += M_TILE) {
            g_tile_expert[nt] = e;
            g_tile_row0[nt] = r;
            nt++;
        }
        off += n;
    }
    g_n_tiles = nt;
}

__global__ void k_fill() {
    int token = blockIdx.x * blockDim.x + threadIdx.x;
    if (token >= B_) return;
#pragma unroll
    for (int k = 0; k < 2; k++) {
        int e = g_top_idx[token * 2 + k];
        int pos = atomicAdd(&g_cursor[e], 1);
        g_assign_token[pos] = token;
        g_slot[token * 2 + k] = pos;
    }
}

__global__ void k_combine(float* __restrict__ y) {
    int i = blockIdx.x * blockDim.x + threadIdx.x;
    if (i >= B_ * (D_ / 4)) return;
    int tok = i / (D_ / 4), q = i % (D_ / 4);
    float g0 = g_top_gate[tok * 2 + 0], g1 = g_top_gate[tok * 2 + 1];
    int s0 = g_slot[tok * 2 + 0], s1 = g_slot[tok * 2 + 1];
    float4 a = *(const float4*)&g_out[(size_t)s0 * D_ + q * 4];
    float4 b = *(const float4*)&g_out[(size_t)s1 * D_ + q * 4];
    float4 v;
    v.x = g0 * a.x + g1 * b.x;
    v.y = g0 * a.y + g1 * b.y;
    v.z = g0 * a.z + g1 * b.z;
    v.w = g0 * a.w + g1 * b.w;
    *(float4*)&y[(size_t)tok * D_ + q * 4] = v;
}

// ---------------- tf32 mma.sync grouped GEMM ----------------
// GATHER=true : A = x (rows gathered by token), C = g_h, GELU applied.
// GATHER=false: A = g_h (bucket rows),          C = g_out.
// Scratch resolved via device symbols in device code only.
// 2 CTAs/SM for latency hiding (barrier + LDG windows interleave across CTAs).
template <bool GATHER, bool GELU>
__global__ void __launch_bounds__(256, 2)
k_moe_gemm(const float* __restrict__ X, const float* __restrict__ W,
           const float* __restrict__ bias, int lda, int ldb, int ldc, int Ktot) {
    const float* A = GATHER ? X : (const float*)g_h;
    float* C = GATHER ? (float*)g_h : (float*)g_out;

    extern __shared__ char smraw[];
    uint32_t sm0 = smem_u32(smraw);
    uint32_t base = (sm0 + 1023) & ~1023u;
    int* sm_tok = (int*)(smraw + (base - sm0) + 2 * STG);

    int tile = blockIdx.y;
    if (tile >= g_n_tiles) return;
    int e = g_tile_expert[tile];
    int row0 = g_tile_row0[tile];
    int off = g_offsets[e];
    int n_e = g_counts[e];
    int col0 = blockIdx.x * N_TILE;
    int t = threadIdx.x;
    int nch = Ktot / K_CHUNK;

    if (t < 128) {
        int r = row0 + t;
        if (r > n_e - 1) r = n_e - 1;
        sm_tok[t] = GATHER ? g_assign_token[off + r] : (off + r);
    }
    __syncthreads();

    // ---- staging thread mapping ----
    int arow = t >> 3;          // 0..31 (+32j)
    int kq = t & 7;             // 16B column
    const float* aptr[4];
#pragma unroll
    for (int j = 0; j < 4; j++)
        aptr[j] = A + (size_t)sm_tok[arow + 32 * j] * lda;

    int bn = t & 127;           // n within tile
    int bkh = (t >> 7) * 16;    // k half
    const float* bptr = W + (size_t)e * Ktot * ldb + col0 + bn;

    float4 av[4];
    float bv[16];

    // ---- compute thread mapping ----
    int wid = t >> 5, lane = t & 31;
    int m0 = (wid & 1) * 64;
    int n0 = (wid >> 1) * 32;
    // ldmatrix address lanes:
    // A x4: m0={rows 0-7,kb+0} m1={rows 8-15,kb+0} m2={rows 0-7,kb+16} m3={rows 8-15,kb+16}
    int a_row_l = (lane & 7) + ((lane >> 3) & 1) * 8;
    int a_kb_l = (lane >> 4) * 16;
    // B x4: m0={n 0-7,kb+0} m1={n 0-7,kb+16} m2={n 8-15,kb+0} m3={n 8-15,kb+16}
    int b_row_l = (lane & 7) + (lane >> 4) * 8;
    int b_kb_l = ((lane >> 3) & 1) * 16;
    int g = lane >> 2, tig = lane & 3;

    float acc[4][4][4];
#pragma unroll
    for (int mt = 0; mt < 4; mt++)
#pragma unroll
        for (int nt = 0; nt < 4; nt++)
#pragma unroll
            for (int i = 0; i < 4; i++) acc[mt][nt][i] = 0.0f;

    uint32_t af[4][4], bfr[4][2];

#define LDG_CHUNK(c)                                                          \
    {                                                                         \
        int k0_ = (c) * K_CHUNK;                                              \
        _Pragma("unroll") for (int j = 0; j < 4; j++)                         \
            av[j] = *(const float4*)(aptr[j] + k0_ + kq * 4);                 \
        _Pragma("unroll") for (int i = 0; i < 16; i++)                        \
            bv[i] = bptr[(size_t)(k0_ + bkh + i) * ldb];                      \
    }
#define STS_CHUNK(s)                                                          \
    {                                                                         \
        uint32_t ab_ = base + (s) * STG, bb_ = ab_ + A_SZ;                    \
        _Pragma("unroll") for (int j = 0; j < 4; j++) {                       \
            float4 v = av[j];                                                 \
            v.x = tf32r(v.x); v.y = tf32r(v.y);                               \
            v.z = tf32r(v.z); v.w = tf32r(v.w);                               \
            sts128(swz_addr(ab_, arow + 32 * j, kq << 4), v);                 \
        }                                                                     \
        _Pragma("unroll") for (int g4 = 0; g4 < 4; g4++) {                    \
            float4 v;                                                         \
            v.x = tf32r(bv[4 * g4 + 0]); v.y = tf32r(bv[4 * g4 + 1]);         \
            v.z = tf32r(bv[4 * g4 + 2]); v.w = tf32r(bv[4 * g4 + 3]);         \
            sts128(swz_addr(bb_, bn, (bkh + 4 * g4) << 2), v);                \
        }                                                                     \
    }

    LDG_CHUNK(0);
    STS_CHUNK(0);
    LDG_CHUNK(1);

    for (int c = 0; c < nch; c++) {
        __syncthreads();
        if (c + 1 < nch) STS_CHUNK((c + 1) & 1);
        if (c + 2 < nch) LDG_CHUNK(c + 2);
        uint32_t ab_ = base + (c & 1) * STG;
        uint32_t bb_ = ab_ + A_SZ;
#pragma unroll
        for (int ks = 0; ks < 4; ks++) {
            int kb = ks * 32;
            // A fragments: one ldmatrix.x4 per 16-row m-tile covers
            // a0=(g,tig) a1=(g+8,tig) a2=(g,tig+4) a3=(g+8,tig+4)
#pragma unroll
            for (int mt = 0; mt < 4; mt++)
                ldsm4(af[mt], swz_addr(ab_, m0 + mt * 16 + a_row_l, kb + a_kb_l));
            // B fragments: one ldmatrix.x4 covers two n-tiles (b0,b1 each)
#pragma unroll
            for (int nt2 = 0; nt2 < 2; nt2++) {
                uint32_t r4[4];
                ldsm4(r4, swz_addr(bb_, n0 + nt2 * 16 + b_row_l, kb + b_kb_l));
                bfr[2 * nt2 + 0][0] = r4[0]; bfr[2 * nt2 + 0][1] = r4[1];
                bfr[2 * nt2 + 1][0] = r4[2]; bfr[2 * nt2 + 1][1] = r4[3];
            }
#pragma unroll
            for (int mt = 0; mt < 4; mt++)
#pragma unroll
                for (int nt = 0; nt < 4; nt++)
                    mma8(acc[mt][nt], af[mt], bfr[nt]);
        }
    }

    // ---- epilogue ----
    // c0=(g,2t) c1=(g,2t+1) c2=(g+8,2t) c3=(g+8,2t+1)
    const float* brow = bias + (size_t)e * ldb + col0;
    float2 bz[4];
#pragma unroll
    for (int nt = 0; nt < 4; nt++) {
        int col = n0 + nt * 8 + 2 * tig;
        bz[nt].x = brow[col];
        bz[nt].y = brow[col + 1];
    }
#pragma unroll
    for (int mt = 0; mt < 4; mt++) {
#pragma unroll
        for (int h = 0; h < 2; h++) {
            int r = row0 + m0 + mt * 16 + g + h * 8;
            if (r < n_e) {
                float* crow = C + (size_t)(off + r) * ldc + col0;
#pragma unroll
                for (int nt = 0; nt < 4; nt++) {
                    float v0 = acc[mt][nt][h * 2 + 0] + bz[nt].x;
                    float v1 = acc[mt][nt][h * 2 + 1] + bz[nt].y;
                    if (GELU) { v0 = gelu_exact(v0); v1 = gelu_exact(v1); }
                    float2 o; o.x = v0; o.y = v1;
                    *(float2*)(crow + n0 + nt * 8 + 2 * tig) = o;
                }
            }
        }
    }
#undef LDG_CHUNK
#undef STS_CHUNK
}

// ---------------- launch ----------------
extern "C" void kernel_launch(void* const* d_in, const int* in_sizes, int n_in,
                              void* d_out, int out_size) {
    const float* x     = (const float*)d_in[0];
    const float* wgate = (const float*)d_in[1];
    const float* W1    = (const float*)d_in[2];
    const float* b1    = (const float*)d_in[3];
    const float* W2    = (const float*)d_in[4];
    const float* b2    = (const float*)d_in[5];
    float* y = (float*)d_out;

    cudaFuncSetAttribute(k_moe_gemm<true, true>,
                         cudaFuncAttributeMaxDynamicSharedMemorySize, SMEM_BYTES);
    cudaFuncSetAttribute(k_moe_gemm<false, false>,
                         cudaFuncAttributeMaxDynamicSharedMemorySize, SMEM_BYTES);

    k_init<<<1, 32>>>();
    k_gate<<<B_ / 256, 256>>>(x, wgate);
    k_scan<<<1, 1>>>();
    k_fill<<<(B_ + 255) / 256, 256>>>();

    // GEMM1: A=x (gather), W=W1 [D,H], C=g_h  — lda=D, ldb=H, ldc=H, Ktot=D
    dim3 g1(H_ / N_TILE, MAX_TILES);   // (16, 136)
    k_moe_gemm<true, true><<<g1, 256, SMEM_BYTES>>>(x, W1, b1, D_, H_, H_, D_);
    // GEMM2: A=g_h, W=W2 [H,D], C=g_out — lda=H, ldb=D, ldc=D, Ktot=H
    dim3 g2(D_ / N_TILE, MAX_TILES);   // (4, 136)
    k_moe_gemm<false, false><<<g2, 256, SMEM_BYTES>>>(x, W2, b2, H_, D_, D_, H_);

    k_combine<<<(B_ * (D_ / 4) + 255) / 256, 256>>>(y);
}

// round 12
// speedup vs baseline: 4.1676x; 1.3632x over previous
#include <cuda_runtime.h>
#include <cstdint>
#include <math.h>

// Shapes: x[B,D], w_gate[D,E], W1[E,D,H], b1[E,H], W2[E,H,D], b2[E,D]
constexpr int B_ = 8192, D_ = 512, E_ = 8, H_ = 2048;
constexpr int NA = B_ * 2;                 // top-2 assignments = 16384

// GEMM tiling (mma.sync tf32 path, cp.async 3-stage)
constexpr int M_TILE = 128, N_TILE = 128, K_CHUNK = 32, STAGES = 3;
constexpr int MAX_TILES = NA / M_TILE + E_;      // 136
constexpr int A_SZ = M_TILE * K_CHUNK * 4;       // 16384 (K-major, 128B rows)
constexpr int B_SZ = N_TILE * K_CHUNK * 4;       // 16384 ([n][k] K-major)
constexpr int STG = A_SZ + B_SZ;                 // 32768 per stage
constexpr int SMEM_BYTES = STAGES * STG + 512 + 1024;

// ---------------- device scratch (device symbols; used only in device code) --
__device__ float g_h[(size_t)NA * H_];     // tf32r(gelu(xW1+b1)) per assignment
__device__ float g_out[(size_t)NA * D_];   // per-assignment expert output
__device__ float g_xr[(size_t)B_ * D_];    // tf32-rounded x
__device__ float g_w1t[(size_t)E_ * D_ * H_];  // W1 transposed [E][H][D], rounded
__device__ float g_w2t[(size_t)E_ * H_ * D_];  // W2 transposed [E][D][H], rounded
__device__ int   g_top_idx[NA];
__device__ float g_top_gate[NA];
__device__ int   g_slot[NA];
__device__ int   g_counts[E_], g_offsets[E_], g_cursor[E_];
__device__ int   g_assign_token[NA];
__device__ int   g_tile_expert[MAX_TILES], g_tile_row0[MAX_TILES];
__device__ int   g_n_tiles;

// ---------------- helpers ----------------
__device__ __forceinline__ uint32_t smem_u32(const void* p) {
    uint32_t a;
    asm("{ .reg .u64 t; cvta.to.shared.u64 t, %1; cvt.u32.u64 %0, t; }" : "=r"(a) : "l"(p));
    return a;
}
// K-major SW128 tile addressing: row has 128B (32 floats); atoms of 8 rows x 128B.
__device__ __forceinline__ uint32_t swz_addr(uint32_t tile_base, int row, int kbyte) {
    return tile_base + (((row & 7) << 7) | ((row >> 3) << 10)) + (kbyte ^ ((row & 7) << 4));
}
__device__ __forceinline__ float tf32r(float x) {
    float r; asm("cvt.rna.tf32.f32 %0, %1;" : "=f"(r) : "f"(x)); return r;
}
__device__ __forceinline__ void cpasync16(uint32_t dst, const void* src) {
    asm volatile("cp.async.cg.shared.global [%0], [%1], 16;"
                 :: "r"(dst), "l"(src) : "memory");
}
__device__ __forceinline__ void cp_commit() {
    asm volatile("cp.async.commit_group;" ::: "memory");
}
__device__ __forceinline__ void cp_wait1() {
    asm volatile("cp.async.wait_group 1;" ::: "memory");
}
__device__ __forceinline__ void ldsm4(uint32_t* r, uint32_t addr) {
    asm volatile("ldmatrix.sync.aligned.m8n8.x4.shared.b16 {%0,%1,%2,%3}, [%4];"
                 : "=r"(r[0]), "=r"(r[1]), "=r"(r[2]), "=r"(r[3]) : "r"(addr));
}
__device__ __forceinline__ void mma8(float* d, const uint32_t* a, const uint32_t* b) {
    asm volatile(
        "mma.sync.aligned.m16n8k8.row.col.f32.tf32.tf32.f32 "
        "{%0,%1,%2,%3}, {%4,%5,%6,%7}, {%8,%9}, {%0,%1,%2,%3};"
        : "+f"(d[0]), "+f"(d[1]), "+f"(d[2]), "+f"(d[3])
        : "r"(a[0]), "r"(a[1]), "r"(a[2]), "r"(a[3]), "r"(b[0]), "r"(b[1]));
}
__device__ __forceinline__ float gelu_exact(float v) {
    return 0.5f * v * (1.0f + erff(v * 0.70710678118654752f));
}

// ---------------- small kernels ----------------
__global__ void k_init() {
    if (threadIdx.x < E_) g_counts[threadIdx.x] = 0;
}

__global__ void k_round_x(const float* __restrict__ x) {
    int i = blockIdx.x * blockDim.x + threadIdx.x;
    if (i >= B_ * D_ / 4) return;
    float4 v = *(const float4*)&x[i * 4];
    v.x = tf32r(v.x); v.y = tf32r(v.y); v.z = tf32r(v.z); v.w = tf32r(v.w);
    *(float4*)&g_xr[i * 4] = v;
}

// src [E][K][N] -> dst [E][N][K], tf32-rounded. block (32,8), grid (N/32, K/32, E)
__global__ void k_transpose_w(const float* __restrict__ src, int K, int N, int which) {
    __shared__ float tile[32][33];
    float* dst = which == 0 ? (float*)g_w1t : (float*)g_w2t;
    int e = blockIdx.z;
    int n0 = blockIdx.x * 32, k0 = blockIdx.y * 32;
    const float* s = src + (size_t)e * K * N;
    float* d = dst + (size_t)e * K * N;
    int tx = threadIdx.x, ty = threadIdx.y;
#pragma unroll
    for (int i = 0; i < 4; i++)
        tile[ty + 8 * i][tx] = s[(size_t)(k0 + ty + 8 * i) * N + n0 + tx];
    __syncthreads();
#pragma unroll
    for (int i = 0; i < 4; i++)
        d[(size_t)(n0 + ty + 8 * i) * K + k0 + tx] = tf32r(tile[tx][ty + 8 * i]);
}

__global__ void k_gate(const float* __restrict__ x, const float* __restrict__ wgate) {
    __shared__ float wg[D_ * E_];
    __shared__ float xs[256 * 17];
    int t = threadIdx.x;
    int token = blockIdx.x * 256 + t;
    for (int i = t; i < D_ * E_; i += 256) wg[i] = wgate[i];
    float logit[E_];
#pragma unroll
    for (int e = 0; e < E_; e++) logit[e] = 0.0f;
    for (int k0 = 0; k0 < D_; k0 += 16) {
        __syncthreads();
#pragma unroll
        for (int i = 0; i < 16; i++) {
            int idx = t + i * 256;
            int r = idx >> 4, c = idx & 15;
            xs[r * 17 + c] = x[(size_t)(blockIdx.x * 256 + r) * D_ + k0 + c];
        }
        __syncthreads();
#pragma unroll
        for (int c = 0; c < 16; c++) {
            float xv = xs[t * 17 + c];
            const float* wrow = &wg[(k0 + c) * E_];
#pragma unroll
            for (int e = 0; e < E_; e++) logit[e] = fmaf(xv, wrow[e], logit[e]);
        }
    }
    float v0 = logit[0]; int i0 = 0;
#pragma unroll
    for (int e = 1; e < E_; e++) if (logit[e] > v0) { v0 = logit[e]; i0 = e; }
    float v1 = -3.4e38f; int i1 = 0;
#pragma unroll
    for (int e = 0; e < E_; e++) if (e != i0 && logit[e] > v1) { v1 = logit[e]; i1 = e; }
    float e1 = __expf(v1 - v0);
    float inv = 1.0f / (1.0f + e1);
    g_top_idx[token * 2 + 0] = i0;
    g_top_idx[token * 2 + 1] = i1;
    g_top_gate[token * 2 + 0] = inv;
    g_top_gate[token * 2 + 1] = e1 * inv;
    atomicAdd(&g_counts[i0], 1);
    atomicAdd(&g_counts[i1], 1);
}

__global__ void k_scan() {
    int off = 0, nt = 0;
    for (int e = 0; e < E_; e++) {
        g_offsets[e] = off;
        g_cursor[e] = off;
        int n = g_counts[e];
        for (int r = 0; r < n; r += M_TILE) {
            g_tile_expert[nt] = e;
            g_tile_row0[nt] = r;
            nt++;
        }
        off += n;
    }
    g_n_tiles = nt;
}

__global__ void k_fill() {
    int token = blockIdx.x * blockDim.x + threadIdx.x;
    if (token >= B_) return;
#pragma unroll
    for (int k = 0; k < 2; k++) {
        int e = g_top_idx[token * 2 + k];
        int pos = atomicAdd(&g_cursor[e], 1);
        g_assign_token[pos] = token;
        g_slot[token * 2 + k] = pos;
    }
}

__global__ void k_combine(float* __restrict__ y) {
    int i = blockIdx.x * blockDim.x + threadIdx.x;
    if (i >= B_ * (D_ / 4)) return;
    int tok = i / (D_ / 4), q = i % (D_ / 4);
    float g0 = g_top_gate[tok * 2 + 0], g1 = g_top_gate[tok * 2 + 1];
    int s0 = g_slot[tok * 2 + 0], s1 = g_slot[tok * 2 + 1];
    float4 a = *(const float4*)&g_out[(size_t)s0 * D_ + q * 4];
    float4 b = *(const float4*)&g_out[(size_t)s1 * D_ + q * 4];
    float4 v;
    v.x = g0 * a.x + g1 * b.x;
    v.y = g0 * a.y + g1 * b.y;
    v.z = g0 * a.z + g1 * b.z;
    v.w = g0 * a.w + g1 * b.w;
    *(float4*)&y[(size_t)tok * D_ + q * 4] = v;
}

// ---------------- tf32 mma.sync grouped GEMM, cp.async 3-stage --------------
// GATHER=true : A = g_xr (gather rows), B = g_w1t [E][H][D], C = g_h (+gelu,rounded)
// GATHER=false: A = g_h (bucket rows),  B = g_w2t [E][D][H], C = g_out
// All operands are pre-rounded tf32 -> mainloop is pure cp.async + ldmatrix + mma.
template <bool GATHER, bool GELU>
__global__ void __launch_bounds__(256, 2)
k_moe_gemm(const float* __restrict__ bias, int lda, int ncols, int Ktot) {
    const float* A = GATHER ? (const float*)g_xr : (const float*)g_h;
    const float* Bt = GATHER ? (const float*)g_w1t : (const float*)g_w2t;
    float* C = GATHER ? (float*)g_h : (float*)g_out;
    int ldc = GATHER ? H_ : D_;

    extern __shared__ char smraw[];
    uint32_t sm0 = smem_u32(smraw);
    uint32_t base = (sm0 + 1023) & ~1023u;
    int* sm_tok = (int*)(smraw + (base - sm0) + STAGES * STG);

    int tile = blockIdx.y;
    if (tile >= g_n_tiles) return;
    int e = g_tile_expert[tile];
    int row0 = g_tile_row0[tile];
    int off = g_offsets[e];
    int n_e = g_counts[e];
    int col0 = blockIdx.x * N_TILE;
    int t = threadIdx.x;
    int nch = Ktot / K_CHUNK;

    if (t < 128) {
        int r = row0 + t;
        if (r > n_e - 1) r = n_e - 1;
        sm_tok[t] = GATHER ? g_assign_token[off + r] : (off + r);
    }
    __syncthreads();

    // ---- async staging mapping: row=(t>>3)+32j, 16B seg=t&7 (A and B identical)
    int srow = t >> 3;
    int skq = t & 7;
    const float* aptr[4];
#pragma unroll
    for (int j = 0; j < 4; j++)
        aptr[j] = A + (size_t)sm_tok[srow + 32 * j] * lda + skq * 4;
    const float* bptr = Bt + (size_t)e * ncols * Ktot
                      + (size_t)(col0 + srow) * Ktot + skq * 4;

#define ISSUE(c, s)                                                           \
    {                                                                         \
        int k0_ = (c) * K_CHUNK;                                              \
        uint32_t ab_ = base + (s) * STG, bb_ = ab_ + A_SZ;                    \
        _Pragma("unroll") for (int j = 0; j < 4; j++) {                       \
            int row = srow + 32 * j;                                          \
            cpasync16(swz_addr(ab_, row, skq << 4), aptr[j] + k0_);           \
            cpasync16(swz_addr(bb_, row, skq << 4),                           \
                      bptr + (size_t)(32 * j) * Ktot + k0_);                  \
        }                                                                     \
    }

    // ---- compute thread mapping ----
    int wid = t >> 5, lane = t & 31;
    int m0 = (wid & 1) * 64;
    int n0 = (wid >> 1) * 32;
    int a_row_l = (lane & 7) + ((lane >> 3) & 1) * 8;
    int a_kb_l = (lane >> 4) * 16;
    int b_row_l = (lane & 7) + (lane >> 4) * 8;
    int b_kb_l = ((lane >> 3) & 1) * 16;
    int g = lane >> 2, tig = lane & 3;

    float acc[4][4][4];
#pragma unroll
    for (int mt = 0; mt < 4; mt++)
#pragma unroll
        for (int nt = 0; nt < 4; nt++)
#pragma unroll
            for (int i = 0; i < 4; i++) acc[mt][nt][i] = 0.0f;

    uint32_t af[4][4], bfr[4][2];

    // prologue: issue chunks 0,1
    ISSUE(0, 0); cp_commit();
    ISSUE(1, 1); cp_commit();

    int comp_s = 0, issue_s = 2;
    for (int c = 0; c < nch; c++) {
        cp_wait1();                // chunk c's group complete (<=1 pending)
        __syncthreads();
        if (c + 2 < nch) { ISSUE(c + 2, issue_s); }
        cp_commit();               // empty group OK on tail
        if (++issue_s == STAGES) issue_s = 0;

        uint32_t ab_ = base + comp_s * STG;
        uint32_t bb_ = ab_ + A_SZ;
        if (++comp_s == STAGES) comp_s = 0;
#pragma unroll
        for (int ks = 0; ks < 4; ks++) {
            int kb = ks * 32;
#pragma unroll
            for (int mt = 0; mt < 4; mt++)
                ldsm4(af[mt], swz_addr(ab_, m0 + mt * 16 + a_row_l, kb + a_kb_l));
#pragma unroll
            for (int nt2 = 0; nt2 < 2; nt2++) {
                uint32_t r4[4];
                ldsm4(r4, swz_addr(bb_, n0 + nt2 * 16 + b_row_l, kb + b_kb_l));
                bfr[2 * nt2 + 0][0] = r4[0]; bfr[2 * nt2 + 0][1] = r4[1];
                bfr[2 * nt2 + 1][0] = r4[2]; bfr[2 * nt2 + 1][1] = r4[3];
            }
#pragma unroll
            for (int mt = 0; mt < 4; mt++)
#pragma unroll
                for (int nt = 0; nt < 4; nt++)
                    mma8(acc[mt][nt], af[mt], bfr[nt]);
        }
    }
#undef ISSUE

    // ---- epilogue ----
    const float* brow = bias + (size_t)e * ncols + col0;
    float2 bz[4];
#pragma unroll
    for (int nt = 0; nt < 4; nt++) {
        int col = n0 + nt * 8 + 2 * tig;
        bz[nt].x = brow[col];
        bz[nt].y = brow[col + 1];
    }
#pragma unroll
    for (int mt = 0; mt < 4; mt++) {
#pragma unroll
        for (int h = 0; h < 2; h++) {
            int r = row0 + m0 + mt * 16 + g + h * 8;
            if (r < n_e) {
                float* crow = C + (size_t)(off + r) * ldc + col0;
#pragma unroll
                for (int nt = 0; nt < 4; nt++) {
                    float v0 = acc[mt][nt][h * 2 + 0] + bz[nt].x;
                    float v1 = acc[mt][nt][h * 2 + 1] + bz[nt].y;
                    if (GELU) {
                        v0 = tf32r(gelu_exact(v0));
                        v1 = tf32r(gelu_exact(v1));
                    }
                    float2 o; o.x = v0; o.y = v1;
                    *(float2*)(crow + n0 + nt * 8 + 2 * tig) = o;
                }
            }
        }
    }
}

// ---------------- launch ----------------
extern "C" void kernel_launch(void* const* d_in, const int* in_sizes, int n_in,
                              void* d_out, int out_size) {
    const float* x     = (const float*)d_in[0];
    const float* wgate = (const float*)d_in[1];
    const float* W1    = (const float*)d_in[2];
    const float* b1    = (const float*)d_in[3];
    const float* W2    = (const float*)d_in[4];
    const float* b2    = (const float*)d_in[5];
    float* y = (float*)d_out;

    cudaFuncSetAttribute(k_moe_gemm<true, true>,
                         cudaFuncAttributeMaxDynamicSharedMemorySize, SMEM_BYTES);
    cudaFuncSetAttribute(k_moe_gemm<false, false>,
                         cudaFuncAttributeMaxDynamicSharedMemorySize, SMEM_BYTES);

    k_init<<<1, 32>>>();
    k_round_x<<<(B_ * D_ / 4 + 255) / 256, 256>>>(x);
    dim3 tb(32, 8);
    k_transpose_w<<<dim3(H_ / 32, D_ / 32, E_), tb>>>(W1, D_, H_, 0);
    k_transpose_w<<<dim3(D_ / 32, H_ / 32, E_), tb>>>(W2, H_, D_, 1);
    k_gate<<<B_ / 256, 256>>>(x, wgate);
    k_scan<<<1, 1>>>();
    k_fill<<<(B_ + 255) / 256, 256>>>();

    // GEMM1: A=g_xr gather, B=g_w1t, C=g_h — lda=D, ncols=H, Ktot=D
    dim3 g1(H_ / N_TILE, MAX_TILES);   // (16, 136)
    k_moe_gemm<true, true><<<g1, 256, SMEM_BYTES>>>(b1, D_, H_, D_);
    // GEMM2: A=g_h, B=g_w2t, C=g_out — lda=H, ncols=D, Ktot=H
    dim3 g2(D_ / N_TILE, MAX_TILES);   // (4, 136)
    k_moe_gemm<false, false><<<g2, 256, SMEM_BYTES>>>(b2, H_, D_, H_);

    k_combine<<<(B_ * (D_ / 4) + 255) / 256, 256>>>(y);
}

// round 13
// speedup vs baseline: 4.1942x; 1.0064x over previous
#include <cuda_runtime.h>
#include <cstdint>
#include <math.h>

// Shapes: x[B,D], w_gate[D,E], W1[E,D,H], b1[E,H], W2[E,H,D], b2[E,D]
constexpr int B_ = 8192, D_ = 512, E_ = 8, H_ = 2048;
constexpr int NA = B_ * 2;                 // top-2 assignments = 16384

// GEMM tiling (mma.sync tf32 path, cp.async 3-stage)
constexpr int M_TILE = 128, N_TILE = 128, K_CHUNK = 32, STAGES = 3;
constexpr int A_SZ = M_TILE * K_CHUNK * 4;       // 16384 (K-major, 128B rows)
constexpr int B_SZ = N_TILE * K_CHUNK * 4;       // 16384 ([n][k] K-major)
constexpr int STG = A_SZ + B_SZ;                 // 32768 per stage
constexpr int SMEM_BYTES = STAGES * STG + 512 + 1024;

// ---------------- device scratch (device symbols; used only in device code) --
__device__ float g_h[(size_t)NA * H_];     // tf32r(gelu(xW1+b1)) per assignment
__device__ float g_out[(size_t)NA * D_];   // per-assignment expert output
__device__ float g_xr[(size_t)B_ * D_];    // tf32-rounded x
__device__ float g_w1t[(size_t)E_ * D_ * H_];  // W1 transposed [E][H][D], rounded
__device__ float g_w2t[(size_t)E_ * H_ * D_];  // W2 transposed [E][D][H], rounded
__device__ int   g_top_idx[NA];
__device__ float g_top_gate[NA];
__device__ int   g_slot[NA];
__device__ int   g_counts[E_], g_cursor[E_];
__device__ int   g_assign_token[NA];

// ---------------- helpers ----------------
__device__ __forceinline__ uint32_t smem_u32(const void* p) {
    uint32_t a;
    asm("{ .reg .u64 t; cvta.to.shared.u64 t, %1; cvt.u32.u64 %0, t; }" : "=r"(a) : "l"(p));
    return a;
}
// K-major SW128 tile addressing: row has 128B (32 floats); atoms of 8 rows x 128B.
__device__ __forceinline__ uint32_t swz_addr(uint32_t tile_base, int row, int kbyte) {
    return tile_base + (((row & 7) << 7) | ((row >> 3) << 10)) + (kbyte ^ ((row & 7) << 4));
}
__device__ __forceinline__ float tf32r(float x) {
    float r; asm("cvt.rna.tf32.f32 %0, %1;" : "=f"(r) : "f"(x)); return r;
}
__device__ __forceinline__ void cpasync16(uint32_t dst, const void* src) {
    asm volatile("cp.async.cg.shared.global [%0], [%1], 16;"
                 :: "r"(dst), "l"(src) : "memory");
}
__device__ __forceinline__ void cp_commit() {
    asm volatile("cp.async.commit_group;" ::: "memory");
}
__device__ __forceinline__ void cp_wait1() {
    asm volatile("cp.async.wait_group 1;" ::: "memory");
}
__device__ __forceinline__ void ldsm4(uint32_t* r, uint32_t addr) {
    asm volatile("ldmatrix.sync.aligned.m8n8.x4.shared.b16 {%0,%1,%2,%3}, [%4];"
                 : "=r"(r[0]), "=r"(r[1]), "=r"(r[2]), "=r"(r[3]) : "r"(addr));
}
__device__ __forceinline__ void mma8(float* d, const uint32_t* a, const uint32_t* b) {
    asm volatile(
        "mma.sync.aligned.m16n8k8.row.col.f32.tf32.tf32.f32 "
        "{%0,%1,%2,%3}, {%4,%5,%6,%7}, {%8,%9}, {%0,%1,%2,%3};"
        : "+f"(d[0]), "+f"(d[1]), "+f"(d[2]), "+f"(d[3])
        : "r"(a[0]), "r"(a[1]), "r"(a[2]), "r"(a[3]), "r"(b[0]), "r"(b[1]));
}
__device__ __forceinline__ float gelu_exact(float v) {
    return 0.5f * v * (1.0f + erff(v * 0.70710678118654752f));
}

// ---------------- k_prep: fused round_x + W1/W2 transpose + counter zero ----
// grid layout (flat blocks of 256 threads):
//   [0, 4096)         : round x (4 floats/thread)
//   [4096, 12288)     : transpose W1 [E][D][H] -> g_w1t [E][H][D]
//   [12288, 20480)    : transpose W2 [E][H][D] -> g_w2t [E][D][H]
__global__ void k_prep(const float* __restrict__ x, const float* __restrict__ W1,
                       const float* __restrict__ W2) {
    int b = blockIdx.x;
    int t = threadIdx.x;
    if (b < 4096) {
        if (b == 0 && t < E_) { g_counts[t] = 0; g_cursor[t] = 0; }
        int i = b * 256 + t;
        float4 v = *(const float4*)&x[(size_t)i * 4];
        v.x = tf32r(v.x); v.y = tf32r(v.y); v.z = tf32r(v.z); v.w = tf32r(v.w);
        *(float4*)&g_xr[(size_t)i * 4] = v;
        return;
    }
    __shared__ float tile[32][33];
    const float* src;
    float* dst;
    int K, N, idx;
    if (b < 12288) { idx = b - 4096;  src = W1; dst = (float*)g_w1t; K = D_; N = H_; }
    else           { idx = b - 12288; src = W2; dst = (float*)g_w2t; K = H_; N = D_; }
    int per_e = (K / 32) * (N / 32);           // 1024 both ways
    int e = idx / per_e, rem = idx % per_e;
    int n0 = (rem % (N / 32)) * 32, k0 = (rem / (N / 32)) * 32;
    const float* s = src + (size_t)e * K * N;
    float* d = dst + (size_t)e * K * N;
    int tx = t & 31, ty = t >> 5;
#pragma unroll
    for (int i = 0; i < 4; i++)
        tile[ty + 8 * i][tx] = s[(size_t)(k0 + ty + 8 * i) * N + n0 + tx];
    __syncthreads();
#pragma unroll
    for (int i = 0; i < 4; i++)
        d[(size_t)(n0 + ty + 8 * i) * K + k0 + tx] = tf32r(tile[tx][ty + 8 * i]);
}

// ---------------- gating ----------------
__global__ void k_gate(const float* __restrict__ x, const float* __restrict__ wgate) {
    __shared__ float wg[D_ * E_];
    __shared__ float xs[256 * 17];
    int t = threadIdx.x;
    int token = blockIdx.x * 256 + t;
    for (int i = t; i < D_ * E_; i += 256) wg[i] = wgate[i];
    float logit[E_];
#pragma unroll
    for (int e = 0; e < E_; e++) logit[e] = 0.0f;
    for (int k0 = 0; k0 < D_; k0 += 16) {
        __syncthreads();
#pragma unroll
        for (int i = 0; i < 16; i++) {
            int idx = t + i * 256;
            int r = idx >> 4, c = idx & 15;
            xs[r * 17 + c] = x[(size_t)(blockIdx.x * 256 + r) * D_ + k0 + c];
        }
        __syncthreads();
#pragma unroll
        for (int c = 0; c < 16; c++) {
            float xv = xs[t * 17 + c];
            const float* wrow = &wg[(k0 + c) * E_];
#pragma unroll
            for (int e = 0; e < E_; e++) logit[e] = fmaf(xv, wrow[e], logit[e]);
        }
    }
    float v0 = logit[0]; int i0 = 0;
#pragma unroll
    for (int e = 1; e < E_; e++) if (logit[e] > v0) { v0 = logit[e]; i0 = e; }
    float v1 = -3.4e38f; int i1 = 0;
#pragma unroll
    for (int e = 0; e < E_; e++) if (e != i0 && logit[e] > v1) { v1 = logit[e]; i1 = e; }
    float e1 = __expf(v1 - v0);
    float inv = 1.0f / (1.0f + e1);
    g_top_idx[token * 2 + 0] = i0;
    g_top_idx[token * 2 + 1] = i1;
    g_top_gate[token * 2 + 0] = inv;
    g_top_gate[token * 2 + 1] = e1 * inv;
    atomicAdd(&g_counts[i0], 1);
    atomicAdd(&g_counts[i1], 1);
}

// ---------------- fill (offsets recomputed inline from g_counts) ----------
__global__ void k_fill() {
    __shared__ int soff[E_];
    if (threadIdx.x == 0) {
        int o = 0;
#pragma unroll
        for (int e = 0; e < E_; e++) { soff[e] = o; o += g_counts[e]; }
    }
    __syncthreads();
    int token = blockIdx.x * blockDim.x + threadIdx.x;
    if (token >= B_) return;
#pragma unroll
    for (int k = 0; k < 2; k++) {
        int e = g_top_idx[token * 2 + k];
        int pos = soff[e] + atomicAdd(&g_cursor[e], 1);
        g_assign_token[pos] = token;
        g_slot[token * 2 + k] = pos;
    }
}

__global__ void k_combine(float* __restrict__ y) {
    int i = blockIdx.x * blockDim.x + threadIdx.x;
    if (i >= B_ * (D_ / 4)) return;
    int tok = i / (D_ / 4), q = i % (D_ / 4);
    float g0 = g_top_gate[tok * 2 + 0], g1 = g_top_gate[tok * 2 + 1];
    int s0 = g_slot[tok * 2 + 0], s1 = g_slot[tok * 2 + 1];
    float4 a = *(const float4*)&g_out[(size_t)s0 * D_ + q * 4];
    float4 b = *(const float4*)&g_out[(size_t)s1 * D_ + q * 4];
    float4 v;
    v.x = g0 * a.x + g1 * b.x;
    v.y = g0 * a.y + g1 * b.y;
    v.z = g0 * a.z + g1 * b.z;
    v.w = g0 * a.w + g1 * b.w;
    *(float4*)&y[(size_t)tok * D_ + q * 4] = v;
}

// ---------------- tf32 mma.sync grouped GEMM, cp.async 3-stage --------------
// grid: (ncols/N_TILE, B_/M_TILE, E_); early exit when row tile beyond bucket.
// GATHER=true : A = g_xr (gather rows), B = g_w1t, C = g_h (+gelu, rounded)
// GATHER=false: A = g_h (bucket rows),  B = g_w2t, C = g_out
template <bool GATHER, bool GELU>
__global__ void __launch_bounds__(256, 2)
k_moe_gemm(const float* __restrict__ bias, int lda, int ncols, int Ktot) {
    int e = blockIdx.z;
    int n_e = g_counts[e];
    int row0 = blockIdx.y * M_TILE;
    if (row0 >= n_e) return;
    int off = 0;
#pragma unroll
    for (int i = 0; i < E_; i++) off += (i < e) ? g_counts[i] : 0;

    const float* A = GATHER ? (const float*)g_xr : (const float*)g_h;
    const float* Bt = GATHER ? (const float*)g_w1t : (const float*)g_w2t;
    float* C = GATHER ? (float*)g_h : (float*)g_out;
    int ldc = GATHER ? H_ : D_;

    extern __shared__ char smraw[];
    uint32_t sm0 = smem_u32(smraw);
    uint32_t base = (sm0 + 1023) & ~1023u;
    int* sm_tok = (int*)(smraw + (base - sm0) + STAGES * STG);

    int col0 = blockIdx.x * N_TILE;
    int t = threadIdx.x;
    int nch = Ktot / K_CHUNK;

    if (t < 128) {
        int r = row0 + t;
        if (r > n_e - 1) r = n_e - 1;
        sm_tok[t] = GATHER ? g_assign_token[off + r] : (off + r);
    }
    __syncthreads();

    // ---- async staging mapping: row=(t>>3)+32j, 16B seg=t&7 (A and B identical)
    int srow = t >> 3;
    int skq = t & 7;
    const float* aptr[4];
#pragma unroll
    for (int j = 0; j < 4; j++)
        aptr[j] = A + (size_t)sm_tok[srow + 32 * j] * lda + skq * 4;
    const float* bptr = Bt + (size_t)e * ncols * Ktot
                      + (size_t)(col0 + srow) * Ktot + skq * 4;

#define ISSUE(c, s)                                                           \
    {                                                                         \
        int k0_ = (c) * K_CHUNK;                                              \
        uint32_t ab_ = base + (s) * STG, bb_ = ab_ + A_SZ;                    \
        _Pragma("unroll") for (int j = 0; j < 4; j++) {                       \
            int row = srow + 32 * j;                                          \
            cpasync16(swz_addr(ab_, row, skq << 4), aptr[j] + k0_);           \
            cpasync16(swz_addr(bb_, row, skq << 4),                           \
                      bptr + (size_t)(32 * j) * Ktot + k0_);                  \
        }                                                                     \
    }

    // ---- compute thread mapping ----
    int wid = t >> 5, lane = t & 31;
    int m0 = (wid & 1) * 64;
    int n0 = (wid >> 1) * 32;
    int a_row_l = (lane & 7) + ((lane >> 3) & 1) * 8;
    int a_kb_l = (lane >> 4) * 16;
    int b_row_l = (lane & 7) + (lane >> 4) * 8;
    int b_kb_l = ((lane >> 3) & 1) * 16;
    int g = lane >> 2, tig = lane & 3;

    float acc[4][4][4];
#pragma unroll
    for (int mt = 0; mt < 4; mt++)
#pragma unroll
        for (int nt = 0; nt < 4; nt++)
#pragma unroll
            for (int i = 0; i < 4; i++) acc[mt][nt][i] = 0.0f;

    uint32_t af[4][4], bfr[4][2];

    ISSUE(0, 0); cp_commit();
    ISSUE(1, 1); cp_commit();

    int comp_s = 0, issue_s = 2;
    for (int c = 0; c < nch; c++) {
        cp_wait1();
        __syncthreads();
        if (c + 2 < nch) { ISSUE(c + 2, issue_s); }
        cp_commit();
        if (++issue_s == STAGES) issue_s = 0;

        uint32_t ab_ = base + comp_s * STG;
        uint32_t bb_ = ab_ + A_SZ;
        if (++comp_s == STAGES) comp_s = 0;
#pragma unroll
        for (int ks = 0; ks < 4; ks++) {
            int kb = ks * 32;
#pragma unroll
            for (int mt = 0; mt < 4; mt++)
                ldsm4(af[mt], swz_addr(ab_, m0 + mt * 16 + a_row_l, kb + a_kb_l));
#pragma unroll
            for (int nt2 = 0; nt2 < 2; nt2++) {
                uint32_t r4[4];
                ldsm4(r4, swz_addr(bb_, n0 + nt2 * 16 + b_row_l, kb + b_kb_l));
                bfr[2 * nt2 + 0][0] = r4[0]; bfr[2 * nt2 + 0][1] = r4[1];
                bfr[2 * nt2 + 1][0] = r4[2]; bfr[2 * nt2 + 1][1] = r4[3];
            }
#pragma unroll
            for (int mt = 0; mt < 4; mt++)
#pragma unroll
                for (int nt = 0; nt < 4; nt++)
                    mma8(acc[mt][nt], af[mt], bfr[nt]);
        }
    }
#undef ISSUE

    // ---- epilogue ----
    const float* brow = bias + (size_t)e * ncols + col0;
    float2 bz[4];
#pragma unroll
    for (int nt = 0; nt < 4; nt++) {
        int col = n0 + nt * 8 + 2 * tig;
        bz[nt].x = brow[col];
        bz[nt].y = brow[col + 1];
    }
#pragma unroll
    for (int mt = 0; mt < 4; mt++) {
#pragma unroll
        for (int h = 0; h < 2; h++) {
            int r = row0 + m0 + mt * 16 + g + h * 8;
            if (r < n_e) {
                float* crow = C + (size_t)(off + r) * ldc + col0;
#pragma unroll
                for (int nt = 0; nt < 4; nt++) {
                    float v0 = acc[mt][nt][h * 2 + 0] + bz[nt].x;
                    float v1 = acc[mt][nt][h * 2 + 1] + bz[nt].y;
                    if (GELU) {
                        v0 = tf32r(gelu_exact(v0));
                        v1 = tf32r(gelu_exact(v1));
                    }
                    float2 o; o.x = v0; o.y = v1;
                    *(float2*)(crow + n0 + nt * 8 + 2 * tig) = o;
                }
            }
        }
    }
}

// ---------------- launch ----------------
extern "C" void kernel_launch(void* const* d_in, const int* in_sizes, int n_in,
                              void* d_out, int out_size) {
    const float* x     = (const float*)d_in[0];
    const float* wgate = (const float*)d_in[1];
    const float* W1    = (const float*)d_in[2];
    const float* b1    = (const float*)d_in[3];
    const float* W2    = (const float*)d_in[4];
    const float* b2    = (const float*)d_in[5];
    float* y = (float*)d_out;

    cudaFuncSetAttribute(k_moe_gemm<true, true>,
                         cudaFuncAttributeMaxDynamicSharedMemorySize, SMEM_BYTES);
    cudaFuncSetAttribute(k_moe_gemm<false, false>,
                         cudaFuncAttributeMaxDynamicSharedMemorySize, SMEM_BYTES);

    k_prep<<<20480, 256>>>(x, W1, W2);                       // launch 0
    k_gate<<<B_ / 256, 256>>>(x, wgate);                     // launch 1
    k_fill<<<(B_ + 255) / 256, 256>>>();                     // launch 2

    // launch 3 (profiled by ncu): GEMM1 — A=g_xr gather, B=g_w1t, C=g_h
    dim3 g1(H_ / N_TILE, B_ / M_TILE, E_);   // (16, 64, 8)
    k_moe_gemm<true, true><<<g1, 256, SMEM_BYTES>>>(b1, D_, H_, D_);
    // launch 4: GEMM2 — A=g_h, B=g_w2t, C=g_out
    dim3 g2(D_ / N_TILE, B_ / M_TILE, E_);   // (4, 64, 8)
    k_moe_gemm<false, false><<<g2, 256, SMEM_BYTES>>>(b2, H_, D_, H_);

    k_combine<<<(B_ * (D_ / 4) + 255) / 256, 256>>>(y);      // launch 5
}

// round 14
// speedup vs baseline: 4.3103x; 1.0277x over previous
#include <cuda_runtime.h>
#include <cstdint>
#include <math.h>

// Shapes: x[B,D], w_gate[D,E], W1[E,D,H], b1[E,H], W2[E,H,D], b2[E,D]
constexpr int B_ = 8192, D_ = 512, E_ = 8, H_ = 2048;
constexpr int NA = B_ * 2;                 // top-2 assignments = 16384

// GEMM tiling (mma.sync tf32 path, cp.async 3-stage)
constexpr int M_TILE = 128, N_TILE = 128, K_CHUNK = 32, STAGES = 3;
constexpr int A_SZ = M_TILE * K_CHUNK * 4;       // 16384 (K-major, 128B rows)
constexpr int B_SZ = N_TILE * K_CHUNK * 4;       // 16384 ([n][k] K-major)
constexpr int STG = A_SZ + B_SZ;                 // 32768 per stage
constexpr int SMEM_BYTES = STAGES * STG + 512 + 1024;

// ---------------- device scratch (device symbols; used only in device code) --
__device__ float g_h[(size_t)NA * H_];     // tf32r(gelu(xW1+b1)) per assignment
__device__ float g_out[(size_t)NA * D_];   // per-assignment expert output
__device__ float g_xr[(size_t)B_ * D_];    // tf32-rounded x
__device__ float g_w1t[(size_t)E_ * D_ * H_];  // W1 transposed [E][H][D], rounded
__device__ float g_w2t[(size_t)E_ * H_ * D_];  // W2 transposed [E][D][H], rounded
__device__ int   g_top_idx[NA];
__device__ float g_top_gate[NA];
__device__ int   g_slot[NA];
__device__ int   g_counts[E_], g_cursor[E_];
__device__ int   g_assign_token[NA];

// ---------------- helpers ----------------
__device__ __forceinline__ uint32_t smem_u32(const void* p) {
    uint32_t a;
    asm("{ .reg .u64 t; cvta.to.shared.u64 t, %1; cvt.u32.u64 %0, t; }" : "=r"(a) : "l"(p));
    return a;
}
// K-major SW128 tile addressing: row has 128B (32 floats); atoms of 8 rows x 128B.
__device__ __forceinline__ uint32_t swz_addr(uint32_t tile_base, int row, int kbyte) {
    return tile_base + (((row & 7) << 7) | ((row >> 3) << 10)) + (kbyte ^ ((row & 7) << 4));
}
__device__ __forceinline__ float tf32r(float x) {
    float r; asm("cvt.rna.tf32.f32 %0, %1;" : "=f"(r) : "f"(x)); return r;
}
__device__ __forceinline__ void cpasync16(uint32_t dst, const void* src) {
    asm volatile("cp.async.cg.shared.global [%0], [%1], 16;"
                 :: "r"(dst), "l"(src) : "memory");
}
__device__ __forceinline__ void cp_commit() {
    asm volatile("cp.async.commit_group;" ::: "memory");
}
__device__ __forceinline__ void cp_wait1() {
    asm volatile("cp.async.wait_group 1;" ::: "memory");
}
__device__ __forceinline__ void ldsm4(uint32_t* r, uint32_t addr) {
    asm volatile("ldmatrix.sync.aligned.m8n8.x4.shared.b16 {%0,%1,%2,%3}, [%4];"
                 : "=r"(r[0]), "=r"(r[1]), "=r"(r[2]), "=r"(r[3]) : "r"(addr));
}
__device__ __forceinline__ void mma8(float* d, const uint32_t* a, const uint32_t* b) {
    asm volatile(
        "mma.sync.aligned.m16n8k8.row.col.f32.tf32.tf32.f32 "
        "{%0,%1,%2,%3}, {%4,%5,%6,%7}, {%8,%9}, {%0,%1,%2,%3};"
        : "+f"(d[0]), "+f"(d[1]), "+f"(d[2]), "+f"(d[3])
        : "r"(a[0]), "r"(a[1]), "r"(a[2]), "r"(a[3]), "r"(b[0]), "r"(b[1]));
}
__device__ __forceinline__ float gelu_exact(float v) {
    return 0.5f * v * (1.0f + erff(v * 0.70710678118654752f));
}

// ---------------- k_prep: W1/W2 transpose (+ counter zero) ----------------
// blocks [0, 8192): W1 [E][D][H] -> g_w1t [E][H][D]
// blocks [8192, 16384): W2 [E][H][D] -> g_w2t [E][D][H]
__global__ void k_prep(const float* __restrict__ W1, const float* __restrict__ W2) {
    int b = blockIdx.x;
    int t = threadIdx.x;
    if (b == 0 && t < E_) { g_counts[t] = 0; g_cursor[t] = 0; }
    __shared__ float tile[32][33];
    const float* src;
    float* dst;
    int K, N, idx;
    if (b < 8192) { idx = b;        src = W1; dst = (float*)g_w1t; K = D_; N = H_; }
    else          { idx = b - 8192; src = W2; dst = (float*)g_w2t; K = H_; N = D_; }
    int per_e = (K / 32) * (N / 32);           // 1024 both ways
    int e = idx / per_e, rem = idx % per_e;
    int n0 = (rem % (N / 32)) * 32, k0 = (rem / (N / 32)) * 32;
    const float* s = src + (size_t)e * K * N;
    float* d = dst + (size_t)e * K * N;
    int tx = t & 31, ty = t >> 5;
#pragma unroll
    for (int i = 0; i < 4; i++)
        tile[ty + 8 * i][tx] = s[(size_t)(k0 + ty + 8 * i) * N + n0 + tx];
    __syncthreads();
#pragma unroll
    for (int i = 0; i < 4; i++)
        d[(size_t)(n0 + ty + 8 * i) * K + k0 + tx] = tf32r(tile[tx][ty + 8 * i]);
}

// ---------------- gating (also writes tf32-rounded x into g_xr) ------------
__global__ void k_gate(const float* __restrict__ x, const float* __restrict__ wgate) {
    __shared__ float wg[D_ * E_];
    __shared__ float xs[256 * 17];
    int t = threadIdx.x;
    int token = blockIdx.x * 256 + t;
    for (int i = t; i < D_ * E_; i += 256) wg[i] = wgate[i];
    float logit[E_];
#pragma unroll
    for (int e = 0; e < E_; e++) logit[e] = 0.0f;
    for (int k0 = 0; k0 < D_; k0 += 16) {
        __syncthreads();
#pragma unroll
        for (int i = 0; i < 16; i++) {
            int idx = t + i * 256;
            int r = idx >> 4, c = idx & 15;
            float v = x[(size_t)(blockIdx.x * 256 + r) * D_ + k0 + c];
            xs[r * 17 + c] = v;
            g_xr[(size_t)(blockIdx.x * 256 + r) * D_ + k0 + c] = tf32r(v);
        }
        __syncthreads();
#pragma unroll
        for (int c = 0; c < 16; c++) {
            float xv = xs[t * 17 + c];
            const float* wrow = &wg[(k0 + c) * E_];
#pragma unroll
            for (int e = 0; e < E_; e++) logit[e] = fmaf(xv, wrow[e], logit[e]);
        }
    }
    float v0 = logit[0]; int i0 = 0;
#pragma unroll
    for (int e = 1; e < E_; e++) if (logit[e] > v0) { v0 = logit[e]; i0 = e; }
    float v1 = -3.4e38f; int i1 = 0;
#pragma unroll
    for (int e = 0; e < E_; e++) if (e != i0 && logit[e] > v1) { v1 = logit[e]; i1 = e; }
    float e1 = __expf(v1 - v0);
    float inv = 1.0f / (1.0f + e1);
    g_top_idx[token * 2 + 0] = i0;
    g_top_idx[token * 2 + 1] = i1;
    g_top_gate[token * 2 + 0] = inv;
    g_top_gate[token * 2 + 1] = e1 * inv;
    atomicAdd(&g_counts[i0], 1);
    atomicAdd(&g_counts[i1], 1);
}

// ---------------- fill (offsets recomputed inline from g_counts) ----------
__global__ void k_fill() {
    __shared__ int soff[E_];
    if (threadIdx.x == 0) {
        int o = 0;
#pragma unroll
        for (int e = 0; e < E_; e++) { soff[e] = o; o += g_counts[e]; }
    }
    __syncthreads();
    int token = blockIdx.x * blockDim.x + threadIdx.x;
    if (token >= B_) return;
#pragma unroll
    for (int k = 0; k < 2; k++) {
        int e = g_top_idx[token * 2 + k];
        int pos = soff[e] + atomicAdd(&g_cursor[e], 1);
        g_assign_token[pos] = token;
        g_slot[token * 2 + k] = pos;
    }
}

__global__ void k_combine(float* __restrict__ y) {
    int i = blockIdx.x * blockDim.x + threadIdx.x;
    if (i >= B_ * (D_ / 4)) return;
    int tok = i / (D_ / 4), q = i % (D_ / 4);
    float g0 = g_top_gate[tok * 2 + 0], g1 = g_top_gate[tok * 2 + 1];
    int s0 = g_slot[tok * 2 + 0], s1 = g_slot[tok * 2 + 1];
    float4 a = *(const float4*)&g_out[(size_t)s0 * D_ + q * 4];
    float4 b = *(const float4*)&g_out[(size_t)s1 * D_ + q * 4];
    float4 v;
    v.x = g0 * a.x + g1 * b.x;
    v.y = g0 * a.y + g1 * b.y;
    v.z = g0 * a.z + g1 * b.z;
    v.w = g0 * a.w + g1 * b.w;
    *(float4*)&y[(size_t)tok * D_ + q * 4] = v;
}

// ---------------- tf32 mma.sync grouped GEMM, cp.async 3-stage --------------
// grid: (ncols/N_TILE, B_/M_TILE, E_); early exit when row tile beyond bucket.
// LDSM addresses precomputed; per-ks address = (stage_base + rel) ^ (ks*32).
// Valid because stage bases are 1024-aligned, row-part uses bits >=7, and
// kb in {0,32,64,96} occupies bits 5-6 carry-free vs the bit-4 k-halves.
template <bool GATHER, bool GELU>
__global__ void __launch_bounds__(256, 2)
k_moe_gemm(const float* __restrict__ bias, int lda, int ncols, int Ktot) {
    int e = blockIdx.z;
    int n_e = g_counts[e];
    int row0 = blockIdx.y * M_TILE;
    if (row0 >= n_e) return;
    int off = 0;
#pragma unroll
    for (int i = 0; i < E_; i++) off += (i < e) ? g_counts[i] : 0;

    const float* A = GATHER ? (const float*)g_xr : (const float*)g_h;
    const float* Bt = GATHER ? (const float*)g_w1t : (const float*)g_w2t;
    float* C = GATHER ? (float*)g_h : (float*)g_out;
    int ldc = GATHER ? H_ : D_;

    extern __shared__ char smraw[];
    uint32_t sm0 = smem_u32(smraw);
    uint32_t base = (sm0 + 1023) & ~1023u;
    int* sm_tok = (int*)(smraw + (base - sm0) + STAGES * STG);

    int col0 = blockIdx.x * N_TILE;
    int t = threadIdx.x;
    int nch = Ktot / K_CHUNK;

    if (t < 128) {
        int r = row0 + t;
        if (r > n_e - 1) r = n_e - 1;
        sm_tok[t] = GATHER ? g_assign_token[off + r] : (off + r);
    }
    __syncthreads();

    // ---- async staging mapping: row=(t>>3)+32j, 16B seg=t&7 (A and B identical)
    int srow = t >> 3;
    int skq = t & 7;
    const float* aptr[4];
#pragma unroll
    for (int j = 0; j < 4; j++)
        aptr[j] = A + (size_t)sm_tok[srow + 32 * j] * lda + skq * 4;
    const float* bptr = Bt + (size_t)e * ncols * Ktot
                      + (size_t)(col0 + srow) * Ktot + skq * 4;
    // staging smem relative offsets (stage-invariant)
    uint32_t st_a[4], st_b[4];
#pragma unroll
    for (int j = 0; j < 4; j++) {
        st_a[j] = swz_addr(0, srow + 32 * j, skq << 4);
        st_b[j] = swz_addr(A_SZ, srow + 32 * j, skq << 4);
    }

#define ISSUE(c, s)                                                           \
    {                                                                         \
        int k0_ = (c) * K_CHUNK;                                              \
        uint32_t sb_ = base + (s) * STG;                                      \
        _Pragma("unroll") for (int j = 0; j < 4; j++) {                       \
            cpasync16(sb_ + st_a[j], aptr[j] + k0_);                          \
            cpasync16(sb_ + st_b[j], bptr + (size_t)(32 * j) * Ktot + k0_);   \
        }                                                                     \
    }

    // ---- compute thread mapping ----
    int wid = t >> 5, lane = t & 31;
    int m0 = (wid & 1) * 64;
    int n0 = (wid >> 1) * 32;
    int a_row_l = (lane & 7) + ((lane >> 3) & 1) * 8;
    int a_kb_l = (lane >> 4) * 16;
    int b_row_l = (lane & 7) + (lane >> 4) * 8;
    int b_kb_l = ((lane >> 3) & 1) * 16;
    int g = lane >> 2, tig = lane & 3;

    // precomputed LDSM relative addresses (stage- and ks-invariant part)
    uint32_t ra[4], rb[2];
#pragma unroll
    for (int mt = 0; mt < 4; mt++)
        ra[mt] = swz_addr(0, m0 + mt * 16 + a_row_l, a_kb_l);
#pragma unroll
    for (int nt2 = 0; nt2 < 2; nt2++)
        rb[nt2] = swz_addr(A_SZ, n0 + nt2 * 16 + b_row_l, b_kb_l);

    float acc[4][4][4];
#pragma unroll
    for (int mt = 0; mt < 4; mt++)
#pragma unroll
        for (int nt = 0; nt < 4; nt++)
#pragma unroll
            for (int i = 0; i < 4; i++) acc[mt][nt][i] = 0.0f;

    uint32_t af[4][4], bfr[4][2];

    ISSUE(0, 0); cp_commit();
    ISSUE(1, 1); cp_commit();

    int comp_s = 0, issue_s = 2;
    for (int c = 0; c < nch; c++) {
        cp_wait1();
        __syncthreads();
        if (c + 2 < nch) { ISSUE(c + 2, issue_s); }
        cp_commit();
        if (++issue_s == STAGES) issue_s = 0;

        uint32_t sb = base + comp_s * STG;
        if (++comp_s == STAGES) comp_s = 0;
        uint32_t a0 = sb + ra[0], a1 = sb + ra[1], a2 = sb + ra[2], a3 = sb + ra[3];
        uint32_t b0 = sb + rb[0], b1 = sb + rb[1];
#pragma unroll
        for (int ks = 0; ks < 4; ks++) {
            uint32_t kbx = ks * 32;   // XOR-fold into bits 5-6
            ldsm4(af[0], a0 ^ kbx);
            ldsm4(af[1], a1 ^ kbx);
            ldsm4(af[2], a2 ^ kbx);
            ldsm4(af[3], a3 ^ kbx);
            {
                uint32_t r4[4];
                ldsm4(r4, b0 ^ kbx);
                bfr[0][0] = r4[0]; bfr[0][1] = r4[1];
                bfr[1][0] = r4[2]; bfr[1][1] = r4[3];
                ldsm4(r4, b1 ^ kbx);
                bfr[2][0] = r4[0]; bfr[2][1] = r4[1];
                bfr[3][0] = r4[2]; bfr[3][1] = r4[3];
            }
#pragma unroll
            for (int mt = 0; mt < 4; mt++)
#pragma unroll
                for (int nt = 0; nt < 4; nt++)
                    mma8(acc[mt][nt], af[mt], bfr[nt]);
        }
    }
#undef ISSUE

    // ---- epilogue ----
    const float* brow = bias + (size_t)e * ncols + col0;
    float2 bz[4];
#pragma unroll
    for (int nt = 0; nt < 4; nt++) {
        int col = n0 + nt * 8 + 2 * tig;
        bz[nt].x = brow[col];
        bz[nt].y = brow[col + 1];
    }
#pragma unroll
    for (int mt = 0; mt < 4; mt++) {
#pragma unroll
        for (int h = 0; h < 2; h++) {
            int r = row0 + m0 + mt * 16 + g + h * 8;
            if (r < n_e) {
                float* crow = C + (size_t)(off + r) * ldc + col0;
#pragma unroll
                for (int nt = 0; nt < 4; nt++) {
                    float v0 = acc[mt][nt][h * 2 + 0] + bz[nt].x;
                    float v1 = acc[mt][nt][h * 2 + 1] + bz[nt].y;
                    if (GELU) {
                        v0 = tf32r(gelu_exact(v0));
                        v1 = tf32r(gelu_exact(v1));
                    }
                    float2 o; o.x = v0; o.y = v1;
                    *(float2*)(crow + n0 + nt * 8 + 2 * tig) = o;
                }
            }
        }
    }
}

// ---------------- launch ----------------
extern "C" void kernel_launch(void* const* d_in, const int* in_sizes, int n_in,
                              void* d_out, int out_size) {
    const float* x     = (const float*)d_in[0];
    const float* wgate = (const float*)d_in[1];
    const float* W1    = (const float*)d_in[2];
    const float* b1    = (const float*)d_in[3];
    const float* W2    = (const float*)d_in[4];
    const float* b2    = (const float*)d_in[5];
    float* y = (float*)d_out;

    cudaFuncSetAttribute(k_moe_gemm<true, true>,
                         cudaFuncAttributeMaxDynamicSharedMemorySize, SMEM_BYTES);
    cudaFuncSetAttribute(k_moe_gemm<false, false>,
                         cudaFuncAttributeMaxDynamicSharedMemorySize, SMEM_BYTES);

    k_prep<<<16384, 256>>>(W1, W2);                          // launch 0
    k_gate<<<B_ / 256, 256>>>(x, wgate);                     // launch 1 (+ g_xr)
    k_fill<<<(B_ + 255) / 256, 256>>>();                     // launch 2

    // launch 3 (profiled slot): GEMM1 — A=g_xr gather, B=g_w1t, C=g_h
    dim3 g1(H_ / N_TILE, B_ / M_TILE, E_);   // (16, 64, 8)
    k_moe_gemm<true, true><<<g1, 256, SMEM_BYTES>>>(b1, D_, H_, D_);
    // launch 4: GEMM2 — A=g_h, B=g_w2t, C=g_out
    dim3 g2(D_ / N_TILE, B_ / M_TILE, E_);   // (4, 64, 8)
    k_moe_gemm<false, false><<<g2, 256, SMEM_BYTES>>>(b2, H_, D_, H_);

    k_combine<<<(B_ * (D_ / 4) + 255) / 256, 256>>>(y);      // launch 5
}

// round 15
// speedup vs baseline: 4.3891x; 1.0183x over previous
#include <cuda_runtime.h>
#include <cstdint>
#include <math.h>

// Shapes: x[B,D], w_gate[D,E], W1[E,D,H], b1[E,H], W2[E,H,D], b2[E,D]
constexpr int B_ = 8192, D_ = 512, E_ = 8, H_ = 2048;
constexpr int NA = B_ * 2;                 // top-2 assignments = 16384

// GEMM tiling (mma.sync tf32 path, cp.async 3-stage)
constexpr int M_TILE = 128, N_TILE = 128, K_CHUNK = 32, STAGES = 3;
constexpr int A_SZ = M_TILE * K_CHUNK * 4;       // 16384 (K-major, 128B rows)
constexpr int B_SZ = N_TILE * K_CHUNK * 4;       // 16384 ([n][k] K-major)
constexpr int STG = A_SZ + B_SZ;                 // 32768 per stage
constexpr int SMEM_BYTES = STAGES * STG + 512 + 1024;

// ---------------- device scratch (device symbols; used only in device code) --
__device__ float g_h[(size_t)NA * H_];     // tf32r(gelu(xW1+b1)) per assignment
__device__ float g_out[(size_t)NA * D_];   // per-assignment expert output
__device__ float g_xr[(size_t)B_ * D_];    // tf32-rounded x
__device__ float g_w1t[(size_t)E_ * D_ * H_];  // W1 transposed [E][H][D], rounded
__device__ float g_w2t[(size_t)E_ * H_ * D_];  // W2 transposed [E][D][H], rounded
__device__ int   g_top_idx[NA];
__device__ float g_top_gate[NA];
__device__ int   g_slot[NA];
__device__ int   g_counts[E_], g_cursor[E_];
__device__ int   g_assign_token[NA];

// ---------------- helpers ----------------
__device__ __forceinline__ uint32_t smem_u32(const void* p) {
    uint32_t a;
    asm("{ .reg .u64 t; cvta.to.shared.u64 t, %1; cvt.u32.u64 %0, t; }" : "=r"(a) : "l"(p));
    return a;
}
// K-major SW128 tile addressing: row has 128B (32 floats); atoms of 8 rows x 128B.
__device__ __forceinline__ uint32_t swz_addr(uint32_t tile_base, int row, int kbyte) {
    return tile_base + (((row & 7) << 7) | ((row >> 3) << 10)) + (kbyte ^ ((row & 7) << 4));
}
__device__ __forceinline__ float tf32r(float x) {
    float r; asm("cvt.rna.tf32.f32 %0, %1;" : "=f"(r) : "f"(x)); return r;
}
__device__ __forceinline__ void cpasync16(uint32_t dst, const void* src) {
    asm volatile("cp.async.cg.shared.global [%0], [%1], 16;"
                 :: "r"(dst), "l"(src) : "memory");
}
__device__ __forceinline__ void cp_commit() {
    asm volatile("cp.async.commit_group;" ::: "memory");
}
__device__ __forceinline__ void cp_wait1() {
    asm volatile("cp.async.wait_group 1;" ::: "memory");
}
__device__ __forceinline__ void ldsm4(uint32_t* r, uint32_t addr) {
    asm volatile("ldmatrix.sync.aligned.m8n8.x4.shared.b16 {%0,%1,%2,%3}, [%4];"
                 : "=r"(r[0]), "=r"(r[1]), "=r"(r[2]), "=r"(r[3]) : "r"(addr));
}
__device__ __forceinline__ void mma8(float* d, const uint32_t* a, const uint32_t* b) {
    asm volatile(
        "mma.sync.aligned.m16n8k8.row.col.f32.tf32.tf32.f32 "
        "{%0,%1,%2,%3}, {%4,%5,%6,%7}, {%8,%9}, {%0,%1,%2,%3};"
        : "+f"(d[0]), "+f"(d[1]), "+f"(d[2]), "+f"(d[3])
        : "r"(a[0]), "r"(a[1]), "r"(a[2]), "r"(a[3]), "r"(b[0]), "r"(b[1]));
}
__device__ __forceinline__ float gelu_exact(float v) {
    return 0.5f * v * (1.0f + erff(v * 0.70710678118654752f));
}

// ---------------- k_prep: W1/W2 transpose (+ counter zero) ----------------
// blocks [0, 8192): W1 [E][D][H] -> g_w1t [E][H][D]
// blocks [8192, 16384): W2 [E][H][D] -> g_w2t [E][D][H]
__global__ void k_prep(const float* __restrict__ W1, const float* __restrict__ W2) {
    int b = blockIdx.x;
    int t = threadIdx.x;
    if (b == 0 && t < E_) { g_counts[t] = 0; g_cursor[t] = 0; }
    __shared__ float tile[32][33];
    const float* src;
    float* dst;
    int K, N, idx;
    if (b < 8192) { idx = b;        src = W1; dst = (float*)g_w1t; K = D_; N = H_; }
    else          { idx = b - 8192; src = W2; dst = (float*)g_w2t; K = H_; N = D_; }
    int per_e = (K / 32) * (N / 32);           // 1024 both ways
    int e = idx / per_e, rem = idx % per_e;
    int n0 = (rem % (N / 32)) * 32, k0 = (rem / (N / 32)) * 32;
    const float* s = src + (size_t)e * K * N;
    float* d = dst + (size_t)e * K * N;
    int tx = t & 31, ty = t >> 5;
#pragma unroll
    for (int i = 0; i < 4; i++)
        tile[ty + 8 * i][tx] = s[(size_t)(k0 + ty + 8 * i) * N + n0 + tx];
    __syncthreads();
#pragma unroll
    for (int i = 0; i < 4; i++)
        d[(size_t)(n0 + ty + 8 * i) * K + k0 + tx] = tf32r(tile[tx][ty + 8 * i]);
}

// ---------------- gating (also writes tf32-rounded x into g_xr) ------------
__global__ void k_gate(const float* __restrict__ x, const float* __restrict__ wgate) {
    __shared__ float wg[D_ * E_];
    __shared__ float xs[256 * 17];
    int t = threadIdx.x;
    int token = blockIdx.x * 256 + t;
    for (int i = t; i < D_ * E_; i += 256) wg[i] = wgate[i];
    float logit[E_];
#pragma unroll
    for (int e = 0; e < E_; e++) logit[e] = 0.0f;
    for (int k0 = 0; k0 < D_; k0 += 16) {
        __syncthreads();
#pragma unroll
        for (int i = 0; i < 16; i++) {
            int idx = t + i * 256;
            int r = idx >> 4, c = idx & 15;
            float v = x[(size_t)(blockIdx.x * 256 + r) * D_ + k0 + c];
            xs[r * 17 + c] = v;
            g_xr[(size_t)(blockIdx.x * 256 + r) * D_ + k0 + c] = tf32r(v);
        }
        __syncthreads();
#pragma unroll
        for (int c = 0; c < 16; c++) {
            float xv = xs[t * 17 + c];
            const float* wrow = &wg[(k0 + c) * E_];
#pragma unroll
            for (int e = 0; e < E_; e++) logit[e] = fmaf(xv, wrow[e], logit[e]);
        }
    }
    float v0 = logit[0]; int i0 = 0;
#pragma unroll
    for (int e = 1; e < E_; e++) if (logit[e] > v0) { v0 = logit[e]; i0 = e; }
    float v1 = -3.4e38f; int i1 = 0;
#pragma unroll
    for (int e = 0; e < E_; e++) if (e != i0 && logit[e] > v1) { v1 = logit[e]; i1 = e; }
    float e1 = __expf(v1 - v0);
    float inv = 1.0f / (1.0f + e1);
    g_top_idx[token * 2 + 0] = i0;
    g_top_idx[token * 2 + 1] = i1;
    g_top_gate[token * 2 + 0] = inv;
    g_top_gate[token * 2 + 1] = e1 * inv;
    atomicAdd(&g_counts[i0], 1);
    atomicAdd(&g_counts[i1], 1);
}

// ---------------- fill (offsets recomputed inline from g_counts) ----------
__global__ void k_fill() {
    __shared__ int soff[E_];
    if (threadIdx.x == 0) {
        int o = 0;
#pragma unroll
        for (int e = 0; e < E_; e++) { soff[e] = o; o += g_counts[e]; }
    }
    __syncthreads();
    int token = blockIdx.x * blockDim.x + threadIdx.x;
    if (token >= B_) return;
#pragma unroll
    for (int k = 0; k < 2; k++) {
        int e = g_top_idx[token * 2 + k];
        int pos = soff[e] + atomicAdd(&g_cursor[e], 1);
        g_assign_token[pos] = token;
        g_slot[token * 2 + k] = pos;
    }
}

__global__ void k_combine(float* __restrict__ y) {
    int i = blockIdx.x * blockDim.x + threadIdx.x;
    if (i >= B_ * (D_ / 4)) return;
    int tok = i / (D_ / 4), q = i % (D_ / 4);
    float g0 = g_top_gate[tok * 2 + 0], g1 = g_top_gate[tok * 2 + 1];
    int s0 = g_slot[tok * 2 + 0], s1 = g_slot[tok * 2 + 1];
    float4 a = *(const float4*)&g_out[(size_t)s0 * D_ + q * 4];
    float4 b = *(const float4*)&g_out[(size_t)s1 * D_ + q * 4];
    float4 v;
    v.x = g0 * a.x + g1 * b.x;
    v.y = g0 * a.y + g1 * b.y;
    v.z = g0 * a.z + g1 * b.z;
    v.w = g0 * a.w + g1 * b.w;
    *(float4*)&y[(size_t)tok * D_ + q * 4] = v;
}

// ---------------- tf32 mma.sync grouped GEMM, cp.async 3-stage --------------
// grid: (ncols/N_TILE, B_/M_TILE, E_); early exit when row tile beyond bucket.
// Inner loop software-pipelined at the SASS level (asm volatile preserves
// order): issue B0,B1,A0,A1 up front, then interleave remaining A ldsm between
// MMA groups so each HMMA group's operands are >= 1 group ahead.
template <bool GATHER, bool GELU>
__global__ void __launch_bounds__(256, 2)
k_moe_gemm(const float* __restrict__ bias, int lda, int ncols, int Ktot) {
    int e = blockIdx.z;
    int n_e = g_counts[e];
    int row0 = blockIdx.y * M_TILE;
    if (row0 >= n_e) return;
    int off = 0;
#pragma unroll
    for (int i = 0; i < E_; i++) off += (i < e) ? g_counts[i] : 0;

    const float* A = GATHER ? (const float*)g_xr : (const float*)g_h;
    const float* Bt = GATHER ? (const float*)g_w1t : (const float*)g_w2t;
    float* C = GATHER ? (float*)g_h : (float*)g_out;
    int ldc = GATHER ? H_ : D_;

    extern __shared__ char smraw[];
    uint32_t sm0 = smem_u32(smraw);
    uint32_t base = (sm0 + 1023) & ~1023u;
    int* sm_tok = (int*)(smraw + (base - sm0) + STAGES * STG);

    int col0 = blockIdx.x * N_TILE;
    int t = threadIdx.x;
    int nch = Ktot / K_CHUNK;

    if (t < 128) {
        int r = row0 + t;
        if (r > n_e - 1) r = n_e - 1;
        sm_tok[t] = GATHER ? g_assign_token[off + r] : (off + r);
    }
    __syncthreads();

    // ---- async staging mapping: row=(t>>3)+32j, 16B seg=t&7 (A and B identical)
    int srow = t >> 3;
    int skq = t & 7;
    const float* aptr[4];
#pragma unroll
    for (int j = 0; j < 4; j++)
        aptr[j] = A + (size_t)sm_tok[srow + 32 * j] * lda + skq * 4;
    const float* bptr = Bt + (size_t)e * ncols * Ktot
                      + (size_t)(col0 + srow) * Ktot + skq * 4;
    uint32_t st_a[4], st_b[4];
#pragma unroll
    for (int j = 0; j < 4; j++) {
        st_a[j] = swz_addr(0, srow + 32 * j, skq << 4);
        st_b[j] = swz_addr(A_SZ, srow + 32 * j, skq << 4);
    }

#define ISSUE(c, s)                                                           \
    {                                                                         \
        int k0_ = (c) * K_CHUNK;                                              \
        uint32_t sb_ = base + (s) * STG;                                      \
        _Pragma("unroll") for (int j = 0; j < 4; j++) {                       \
            cpasync16(sb_ + st_a[j], aptr[j] + k0_);                          \
            cpasync16(sb_ + st_b[j], bptr + (size_t)(32 * j) * Ktot + k0_);   \
        }                                                                     \
    }

    // ---- compute thread mapping ----
    int wid = t >> 5, lane = t & 31;
    int m0 = (wid & 1) * 64;
    int n0 = (wid >> 1) * 32;
    int a_row_l = (lane & 7) + ((lane >> 3) & 1) * 8;
    int a_kb_l = (lane >> 4) * 16;
    int b_row_l = (lane & 7) + (lane >> 4) * 8;
    int b_kb_l = ((lane >> 3) & 1) * 16;
    int g = lane >> 2, tig = lane & 3;

    uint32_t ra[4], rb[2];
#pragma unroll
    for (int mt = 0; mt < 4; mt++)
        ra[mt] = swz_addr(0, m0 + mt * 16 + a_row_l, a_kb_l);
#pragma unroll
    for (int nt2 = 0; nt2 < 2; nt2++)
        rb[nt2] = swz_addr(A_SZ, n0 + nt2 * 16 + b_row_l, b_kb_l);

    float acc[4][4][4];
#pragma unroll
    for (int mt = 0; mt < 4; mt++)
#pragma unroll
        for (int nt = 0; nt < 4; nt++)
#pragma unroll
            for (int i = 0; i < 4; i++) acc[mt][nt][i] = 0.0f;

    uint32_t af[4][4], bfr[4][2];

    ISSUE(0, 0); cp_commit();
    ISSUE(1, 1); cp_commit();

    int comp_s = 0, issue_s = 2;
    for (int c = 0; c < nch; c++) {
        cp_wait1();
        __syncthreads();
        if (c + 2 < nch) { ISSUE(c + 2, issue_s); }
        cp_commit();
        if (++issue_s == STAGES) issue_s = 0;

        uint32_t sb = base + comp_s * STG;
        if (++comp_s == STAGES) comp_s = 0;
        uint32_t a0 = sb + ra[0], a1 = sb + ra[1], a2 = sb + ra[2], a3 = sb + ra[3];
        uint32_t b0 = sb + rb[0], b1 = sb + rb[1];
#pragma unroll
        for (int ks = 0; ks < 4; ks++) {
            uint32_t kbx = ks * 32;   // XOR-fold into bits 5-6
            // pipeline-friendly issue order: B frags + 2 A frags up front,
            // remaining A frags interleaved between MMA groups.
            {
                uint32_t r4[4];
                ldsm4(r4, b0 ^ kbx);
                bfr[0][0] = r4[0]; bfr[0][1] = r4[1];
                bfr[1][0] = r4[2]; bfr[1][1] = r4[3];
                ldsm4(r4, b1 ^ kbx);
                bfr[2][0] = r4[0]; bfr[2][1] = r4[1];
                bfr[3][0] = r4[2]; bfr[3][1] = r4[3];
            }
            ldsm4(af[0], a0 ^ kbx);
            ldsm4(af[1], a1 ^ kbx);
#pragma unroll
            for (int nt = 0; nt < 4; nt++) mma8(acc[0][nt], af[0], bfr[nt]);
            ldsm4(af[2], a2 ^ kbx);
#pragma unroll
            for (int nt = 0; nt < 4; nt++) mma8(acc[1][nt], af[1], bfr[nt]);
            ldsm4(af[3], a3 ^ kbx);
#pragma unroll
            for (int nt = 0; nt < 4; nt++) mma8(acc[2][nt], af[2], bfr[nt]);
#pragma unroll
            for (int nt = 0; nt < 4; nt++) mma8(acc[3][nt], af[3], bfr[nt]);
        }
    }
#undef ISSUE

    // ---- epilogue ----
    const float* brow = bias + (size_t)e * ncols + col0;
    float2 bz[4];
#pragma unroll
    for (int nt = 0; nt < 4; nt++) {
        int col = n0 + nt * 8 + 2 * tig;
        bz[nt].x = brow[col];
        bz[nt].y = brow[col + 1];
    }
#pragma unroll
    for (int mt = 0; mt < 4; mt++) {
#pragma unroll
        for (int h = 0; h < 2; h++) {
            int r = row0 + m0 + mt * 16 + g + h * 8;
            if (r < n_e) {
                float* crow = C + (size_t)(off + r) * ldc + col0;
#pragma unroll
                for (int nt = 0; nt < 4; nt++) {
                    float v0 = acc[mt][nt][h * 2 + 0] + bz[nt].x;
                    float v1 = acc[mt][nt][h * 2 + 1] + bz[nt].y;
                    if (GELU) {
                        v0 = tf32r(gelu_exact(v0));
                        v1 = tf32r(gelu_exact(v1));
                    }
                    float2 o; o.x = v0; o.y = v1;
                    *(float2*)(crow + n0 + nt * 8 + 2 * tig) = o;
                }
            }
        }
    }
}

// ---------------- launch ----------------
extern "C" void kernel_launch(void* const* d_in, const int* in_sizes, int n_in,
                              void* d_out, int out_size) {
    const float* x     = (const float*)d_in[0];
    const float* wgate = (const float*)d_in[1];
    const float* W1    = (const float*)d_in[2];
    const float* b1    = (const float*)d_in[3];
    const float* W2    = (const float*)d_in[4];
    const float* b2    = (const float*)d_in[5];
    float* y = (float*)d_out;

    cudaFuncSetAttribute(k_moe_gemm<true, true>,
                         cudaFuncAttributeMaxDynamicSharedMemorySize, SMEM_BYTES);
    cudaFuncSetAttribute(k_moe_gemm<false, false>,
                         cudaFuncAttributeMaxDynamicSharedMemorySize, SMEM_BYTES);

    k_prep<<<16384, 256>>>(W1, W2);                          // launch 0
    k_gate<<<B_ / 256, 256>>>(x, wgate);                     // launch 1 (+ g_xr)
    k_fill<<<(B_ + 255) / 256, 256>>>();                     // launch 2

    // launch 3 (profiled slot): GEMM1 — A=g_xr gather, B=g_w1t, C=g_h
    dim3 g1(H_ / N_TILE, B_ / M_TILE, E_);   // (16, 64, 8)
    k_moe_gemm<true, true><<<g1, 256, SMEM_BYTES>>>(b1, D_, H_, D_);
    // launch 4: GEMM2 — A=g_h, B=g_w2t, C=g_out
    dim3 g2(D_ / N_TILE, B_ / M_TILE, E_);   // (4, 64, 8)
    k_moe_gemm<false, false><<<g2, 256, SMEM_BYTES>>>(b2, H_, D_, H_);

    k_combine<<<(B_ * (D_ / 4) + 255) / 256, 256>>>(y);      // launch 5
}

// round 17
// speedup vs baseline: 4.5119x; 1.0280x over previous
#include <cuda_runtime.h>
#include <cstdint>
#include <math.h>

// Shapes: x[B,D], w_gate[D,E], W1[E,D,H], b1[E,H], W2[E,H,D], b2[E,D]
constexpr int B_ = 8192, D_ = 512, E_ = 8, H_ = 2048;
constexpr int NA = B_ * 2;                 // top-2 assignments = 16384

// GEMM tiling (mma.sync tf32 path, cp.async 3-stage)
constexpr int M_TILE = 128, N_TILE = 128, K_CHUNK = 32, STAGES = 3;
constexpr int A_SZ = M_TILE * K_CHUNK * 4;       // 16384 (K-major, 128B rows)
constexpr int B_SZ = N_TILE * K_CHUNK * 4;       // 16384 ([n][k] K-major)
constexpr int STG = A_SZ + B_SZ;                 // 32768 per stage
constexpr int SMEM_BYTES = STAGES * STG + 512 + 1024;

// ---------------- device scratch (device symbols; used only in device code) --
__device__ float g_h[(size_t)NA * H_];     // tf32r(gelu(xW1+b1)) per assignment
__device__ float g_out[(size_t)NA * D_];   // per-assignment expert output
__device__ float g_xr[(size_t)B_ * D_];    // tf32-rounded x
__device__ float g_w1t[(size_t)E_ * D_ * H_];  // W1 transposed [E][H][D], rounded
__device__ float g_w2t[(size_t)E_ * H_ * D_];  // W2 transposed [E][D][H], rounded
__device__ int   g_top_idx[NA];
__device__ float g_top_gate[NA];
__device__ int   g_slot[NA];
__device__ int   g_counts[E_], g_cursor[E_];
__device__ int   g_assign_token[NA];

// ---------------- helpers ----------------
__device__ __forceinline__ uint32_t smem_u32(const void* p) {
    uint32_t a;
    asm("{ .reg .u64 t; cvta.to.shared.u64 t, %1; cvt.u32.u64 %0, t; }" : "=r"(a) : "l"(p));
    return a;
}
// K-major SW128 tile addressing: row has 128B (32 floats); atoms of 8 rows x 128B.
__device__ __forceinline__ uint32_t swz_addr(uint32_t tile_base, int row, int kbyte) {
    return tile_base + (((row & 7) << 7) | ((row >> 3) << 10)) + (kbyte ^ ((row & 7) << 4));
}
__device__ __forceinline__ float tf32r(float x) {
    float r; asm("cvt.rna.tf32.f32 %0, %1;" : "=f"(r) : "f"(x)); return r;
}
__device__ __forceinline__ void cpasync16(uint32_t dst, const void* src) {
    asm volatile("cp.async.cg.shared.global [%0], [%1], 16;"
                 :: "r"(dst), "l"(src) : "memory");
}
__device__ __forceinline__ void cp_commit() {
    asm volatile("cp.async.commit_group;" ::: "memory");
}
__device__ __forceinline__ void cp_wait1() {
    asm volatile("cp.async.wait_group 1;" ::: "memory");
}
__device__ __forceinline__ void ldsm4(uint32_t* r, uint32_t addr) {
    asm volatile("ldmatrix.sync.aligned.m8n8.x4.shared.b16 {%0,%1,%2,%3}, [%4];"
                 : "=r"(r[0]), "=r"(r[1]), "=r"(r[2]), "=r"(r[3]) : "r"(addr));
}
__device__ __forceinline__ void mma8(float* d, const uint32_t* a, const uint32_t* b) {
    asm volatile(
        "mma.sync.aligned.m16n8k8.row.col.f32.tf32.tf32.f32 "
        "{%0,%1,%2,%3}, {%4,%5,%6,%7}, {%8,%9}, {%0,%1,%2,%3};"
        : "+f"(d[0]), "+f"(d[1]), "+f"(d[2]), "+f"(d[3])
        : "r"(a[0]), "r"(a[1]), "r"(a[2]), "r"(a[3]), "r"(b[0]), "r"(b[1]));
}
// tanh-form gelu: v * sigmoid(2t), t = 0.79788456(v + 0.044715 v^3).
// ~8 inst (2 MUFU) vs ~25 for erff. |diff vs erf-gelu| <= ~3e-4 abs.
__device__ __forceinline__ float gelu_fast(float v) {
    float a = v * v;
    float b = fmaf(a, 0.044715f, 1.0f);
    float t = (0.7978845608028654f * v) * b;
    float ez;   // exp(2t) = ex2(2t * log2(e))
    asm("ex2.approx.f32 %0, %1;" : "=f"(ez) : "f"(t * 2.8853900817779268f));
    float s;    // 1 / (exp(2t) + 1)
    asm("rcp.approx.f32 %0, %1;" : "=f"(s) : "f"(ez + 1.0f));
    return fmaf(-v, s, v);     // v * (1 - s)
}

// ---------------- k_prep: W1/W2 transpose (+ counter zero) ----------------
// blocks [0, 8192): W1 [E][D][H] -> g_w1t [E][H][D]
// blocks [8192, 16384): W2 [E][H][D] -> g_w2t [E][D][H]
__global__ void k_prep(const float* __restrict__ W1, const float* __restrict__ W2) {
    int b = blockIdx.x;
    int t = threadIdx.x;
    if (b == 0 && t < E_) { g_counts[t] = 0; g_cursor[t] = 0; }
    __shared__ float tile[32][33];
    const float* src;
    float* dst;
    int K, N, idx;
    if (b < 8192) { idx = b;        src = W1; dst = (float*)g_w1t; K = D_; N = H_; }
    else          { idx = b - 8192; src = W2; dst = (float*)g_w2t; K = H_; N = D_; }
    int per_e = (K / 32) * (N / 32);           // 1024 both ways
    int e = idx / per_e, rem = idx % per_e;
    int n0 = (rem % (N / 32)) * 32, k0 = (rem / (N / 32)) * 32;
    const float* s = src + (size_t)e * K * N;
    float* d = dst + (size_t)e * K * N;
    int tx = t & 31, ty = t >> 5;
#pragma unroll
    for (int i = 0; i < 4; i++)
        tile[ty + 8 * i][tx] = s[(size_t)(k0 + ty + 8 * i) * N + n0 + tx];
    __syncthreads();
#pragma unroll
    for (int i = 0; i < 4; i++)
        d[(size_t)(n0 + ty + 8 * i) * K + k0 + tx] = tf32r(tile[tx][ty + 8 * i]);
}

// ---------------- gating (also writes tf32-rounded x into g_xr) ------------
__global__ void k_gate(const float* __restrict__ x, const float* __restrict__ wgate) {
    __shared__ float wg[D_ * E_];
    __shared__ float xs[256 * 17];
    int t = threadIdx.x;
    int token = blockIdx.x * 256 + t;
    for (int i = t; i < D_ * E_; i += 256) wg[i] = wgate[i];
    float logit[E_];
#pragma unroll
    for (int e = 0; e < E_; e++) logit[e] = 0.0f;
    for (int k0 = 0; k0 < D_; k0 += 16) {
        __syncthreads();
#pragma unroll
        for (int i = 0; i < 16; i++) {
            int idx = t + i * 256;
            int r = idx >> 4, c = idx & 15;
            float v = x[(size_t)(blockIdx.x * 256 + r) * D_ + k0 + c];
            xs[r * 17 + c] = v;
            g_xr[(size_t)(blockIdx.x * 256 + r) * D_ + k0 + c] = tf32r(v);
        }
        __syncthreads();
#pragma unroll
        for (int c = 0; c < 16; c++) {
            float xv = xs[t * 17 + c];
            const float* wrow = &wg[(k0 + c) * E_];
#pragma unroll
            for (int e = 0; e < E_; e++) logit[e] = fmaf(xv, wrow[e], logit[e]);
        }
    }
    float v0 = logit[0]; int i0 = 0;
#pragma unroll
    for (int e = 1; e < E_; e++) if (logit[e] > v0) { v0 = logit[e]; i0 = e; }
    float v1 = -3.4e38f; int i1 = 0;
#pragma unroll
    for (int e = 0; e < E_; e++) if (e != i0 && logit[e] > v1) { v1 = logit[e]; i1 = e; }
    float e1 = __expf(v1 - v0);
    float inv = 1.0f / (1.0f + e1);
    g_top_idx[token * 2 + 0] = i0;
    g_top_idx[token * 2 + 1] = i1;
    g_top_gate[token * 2 + 0] = inv;
    g_top_gate[token * 2 + 1] = e1 * inv;
    atomicAdd(&g_counts[i0], 1);
    atomicAdd(&g_counts[i1], 1);
}

// ---------------- fill (offsets recomputed inline from g_counts) ----------
__global__ void k_fill() {
    __shared__ int soff[E_];
    if (threadIdx.x == 0) {
        int o = 0;
#pragma unroll
        for (int e = 0; e < E_; e++) { soff[e] = o; o += g_counts[e]; }
    }
    __syncthreads();
    int token = blockIdx.x * blockDim.x + threadIdx.x;
    if (token >= B_) return;
#pragma unroll
    for (int k = 0; k < 2; k++) {
        int e = g_top_idx[token * 2 + k];
        int pos = soff[e] + atomicAdd(&g_cursor[e], 1);
        g_assign_token[pos] = token;
        g_slot[token * 2 + k] = pos;
    }
}

__global__ void k_combine(float* __restrict__ y) {
    int i = blockIdx.x * blockDim.x + threadIdx.x;
    if (i >= B_ * (D_ / 4)) return;
    int tok = i / (D_ / 4), q = i % (D_ / 4);
    float g0 = g_top_gate[tok * 2 + 0], g1 = g_top_gate[tok * 2 + 1];
    int s0 = g_slot[tok * 2 + 0], s1 = g_slot[tok * 2 + 1];
    float4 a = *(const float4*)&g_out[(size_t)s0 * D_ + q * 4];
    float4 b = *(const float4*)&g_out[(size_t)s1 * D_ + q * 4];
    float4 v;
    v.x = g0 * a.x + g1 * b.x;
    v.y = g0 * a.y + g1 * b.y;
    v.z = g0 * a.z + g1 * b.z;
    v.w = g0 * a.w + g1 * b.w;
    *(float4*)&y[(size_t)tok * D_ + q * 4] = v;
}

// ---------------- tf32 mma.sync grouped GEMM, cp.async 3-stage --------------
// grid: (ncols/N_TILE, B_/M_TILE, E_); early exit when row tile beyond bucket.
template <bool GATHER, bool GELU>
__global__ void __launch_bounds__(256, 2)
k_moe_gemm(const float* __restrict__ bias, int lda, int ncols, int Ktot) {
    int e = blockIdx.z;
    int n_e = g_counts[e];
    int row0 = blockIdx.y * M_TILE;
    if (row0 >= n_e) return;
    int off = 0;
#pragma unroll
    for (int i = 0; i < E_; i++) off += (i < e) ? g_counts[i] : 0;

    const float* A = GATHER ? (const float*)g_xr : (const float*)g_h;
    const float* Bt = GATHER ? (const float*)g_w1t : (const float*)g_w2t;
    float* C = GATHER ? (float*)g_h : (float*)g_out;
    int ldc = GATHER ? H_ : D_;

    extern __shared__ char smraw[];
    uint32_t sm0 = smem_u32(smraw);
    uint32_t base = (sm0 + 1023) & ~1023u;
    int* sm_tok = (int*)(smraw + (base - sm0) + STAGES * STG);

    int col0 = blockIdx.x * N_TILE;
    int t = threadIdx.x;
    int nch = Ktot / K_CHUNK;

    if (t < 128) {
        int r = row0 + t;
        if (r > n_e - 1) r = n_e - 1;
        sm_tok[t] = GATHER ? g_assign_token[off + r] : (off + r);
    }
    __syncthreads();

    // ---- async staging mapping: row=(t>>3)+32j, 16B seg=t&7 (A and B identical)
    int srow = t >> 3;
    int skq = t & 7;
    const float* aptr[4];
#pragma unroll
    for (int j = 0; j < 4; j++)
        aptr[j] = A + (size_t)sm_tok[srow + 32 * j] * lda + skq * 4;
    const float* bptr = Bt + (size_t)e * ncols * Ktot
                      + (size_t)(col0 + srow) * Ktot + skq * 4;
    uint32_t st_a[4], st_b[4];
#pragma unroll
    for (int j = 0; j < 4; j++) {
        st_a[j] = swz_addr(0, srow + 32 * j, skq << 4);
        st_b[j] = swz_addr(A_SZ, srow + 32 * j, skq << 4);
    }

#define ISSUE(c, s)                                                           \
    {                                                                         \
        int k0_ = (c) * K_CHUNK;                                              \
        uint32_t sb_ = base + (s) * STG;                                      \
        _Pragma("unroll") for (int j = 0; j < 4; j++) {                       \
            cpasync16(sb_ + st_a[j], aptr[j] + k0_);                          \
            cpasync16(sb_ + st_b[j], bptr + (size_t)(32 * j) * Ktot + k0_);   \
        }                                                                     \
    }

    // ---- compute thread mapping ----
    int wid = t >> 5, lane = t & 31;
    int m0 = (wid & 1) * 64;
    int n0 = (wid >> 1) * 32;
    int a_row_l = (lane & 7) + ((lane >> 3) & 1) * 8;
    int a_kb_l = (lane >> 4) * 16;
    int b_row_l = (lane & 7) + (lane >> 4) * 8;
    int b_kb_l = ((lane >> 3) & 1) * 16;
    int g = lane >> 2, tig = lane & 3;

    uint32_t ra[4], rb[2];
#pragma unroll
    for (int mt = 0; mt < 4; mt++)
        ra[mt] = swz_addr(0, m0 + mt * 16 + a_row_l, a_kb_l);
#pragma unroll
    for (int nt2 = 0; nt2 < 2; nt2++)
        rb[nt2] = swz_addr(A_SZ, n0 + nt2 * 16 + b_row_l, b_kb_l);

    float acc[4][4][4];
#pragma unroll
    for (int mt = 0; mt < 4; mt++)
#pragma unroll
        for (int nt = 0; nt < 4; nt++)
#pragma unroll
            for (int i = 0; i < 4; i++) acc[mt][nt][i] = 0.0f;

    uint32_t af[4][4], bfr[4][2];

    ISSUE(0, 0); cp_commit();
    ISSUE(1, 1); cp_commit();

    int comp_s = 0, issue_s = 2;
    for (int c = 0; c < nch; c++) {
        cp_wait1();
        __syncthreads();
        if (c + 2 < nch) { ISSUE(c + 2, issue_s); }
        cp_commit();
        if (++issue_s == STAGES) issue_s = 0;

        uint32_t sb = base + comp_s * STG;
        if (++comp_s == STAGES) comp_s = 0;
        uint32_t a0 = sb + ra[0], a1 = sb + ra[1], a2 = sb + ra[2], a3 = sb + ra[3];
        uint32_t b0 = sb + rb[0], b1 = sb + rb[1];
#pragma unroll
        for (int ks = 0; ks < 4; ks++) {
            uint32_t kbx = ks * 32;   // XOR-fold into bits 5-6
            {
                uint32_t r4[4];
                ldsm4(r4, b0 ^ kbx);
                bfr[0][0] = r4[0]; bfr[0][1] = r4[1];
                bfr[1][0] = r4[2]; bfr[1][1] = r4[3];
                ldsm4(r4, b1 ^ kbx);
                bfr[2][0] = r4[0]; bfr[2][1] = r4[1];
                bfr[3][0] = r4[2]; bfr[3][1] = r4[3];
            }
            ldsm4(af[0], a0 ^ kbx);
            ldsm4(af[1], a1 ^ kbx);
#pragma unroll
            for (int nt = 0; nt < 4; nt++) mma8(acc[0][nt], af[0], bfr[nt]);
            ldsm4(af[2], a2 ^ kbx);
#pragma unroll
            for (int nt = 0; nt < 4; nt++) mma8(acc[1][nt], af[1], bfr[nt]);
            ldsm4(af[3], a3 ^ kbx);
#pragma unroll
            for (int nt = 0; nt < 4; nt++) mma8(acc[2][nt], af[2], bfr[nt]);
#pragma unroll
            for (int nt = 0; nt < 4; nt++) mma8(acc[3][nt], af[3], bfr[nt]);
        }
    }
#undef ISSUE

    // ---- epilogue ----
    const float* brow = bias + (size_t)e * ncols + col0;
    float2 bz[4];
#pragma unroll
    for (int nt = 0; nt < 4; nt++) {
        int col = n0 + nt * 8 + 2 * tig;
        bz[nt].x = brow[col];
        bz[nt].y = brow[col + 1];
    }
#pragma unroll
    for (int mt = 0; mt < 4; mt++) {
#pragma unroll
        for (int h = 0; h < 2; h++) {
            int r = row0 + m0 + mt * 16 + g + h * 8;
            if (r < n_e) {
                float* crow = C + (size_t)(off + r) * ldc + col0;
#pragma unroll
                for (int nt = 0; nt < 4; nt++) {
                    float v0 = acc[mt][nt][h * 2 + 0] + bz[nt].x;
                    float v1 = acc[mt][nt][h * 2 + 1] + bz[nt].y;
                    if (GELU) {
                        v0 = tf32r(gelu_fast(v0));
                        v1 = tf32r(gelu_fast(v1));
                    }
                    float2 o; o.x = v0; o.y = v1;
                    *(float2*)(crow + n0 + nt * 8 + 2 * tig) = o;
                }
            }
        }
    }
}

// ---------------- launch ----------------
extern "C" void kernel_launch(void* const* d_in, const int* in_sizes, int n_in,
                              void* d_out, int out_size) {
    const float* x     = (const float*)d_in[0];
    const float* wgate = (const float*)d_in[1];
    const float* W1    = (const float*)d_in[2];
    const float* b1    = (const float*)d_in[3];
    const float* W2    = (const float*)d_in[4];
    const float* b2    = (const float*)d_in[5];
    float* y = (float*)d_out;

    cudaFuncSetAttribute(k_moe_gemm<true, true>,
                         cudaFuncAttributeMaxDynamicSharedMemorySize, SMEM_BYTES);
    cudaFuncSetAttribute(k_moe_gemm<false, false>,
                         cudaFuncAttributeMaxDynamicSharedMemorySize, SMEM_BYTES);

    k_prep<<<16384, 256>>>(W1, W2);                          // launch 0
    k_gate<<<B_ / 256, 256>>>(x, wgate);                     // launch 1 (+ g_xr)
    k_fill<<<(B_ + 255) / 256, 256>>>();                     // launch 2

    // launch 3 (profiled slot): GEMM1 — A=g_xr gather, B=g_w1t, C=g_h
    dim3 g1(H_ / N_TILE, B_ / M_TILE, E_);   // (16, 64, 8)
    k_moe_gemm<true, true><<<g1, 256, SMEM_BYTES>>>(b1, D_, H_, D_);
    // launch 4: GEMM2 — A=g_h, B=g_w2t, C=g_out
    dim3 g2(D_ / N_TILE, B_ / M_TILE, E_);   // (4, 64, 8)
    k_moe_gemm<false, false><<<g2, 256, SMEM_BYTES>>>(b2, H_, D_, H_);

    k_combine<<<(B_ * (D_ / 4) + 255) / 256, 256>>>(y);      // launch 5
}